// round 5
// baseline (speedup 1.0000x reference)
#include <cuda_runtime.h>
#include <math.h>

#define BATCH 64
#define TLEN  4096
#define BT    (BATCH*TLEN)
#define C     192

// Scratch (device globals: allocation-free per harness rules)
__device__ float g_h0[(size_t)BT*C];    // 201 MB  (ping)
__device__ float g_h1[(size_t)BT*C];    // 201 MB  (pong)
__device__ float g_p[(size_t)BT*32];    // 32 MB
__device__ float g_lad[BT];             // 1 MB

__device__ __forceinline__ float geluf(float u) {
    return 0.5f*u*(1.f + erff(u*0.7071067811865475f));
}

// ---------------------------------------------------------------------------
// Fused layer: per block of 32 positions (128 thr, 4 warps, 8 rows/warp)
//  phase 1: W kb=0 tile -> smem buf0 ; dw+LN1+gelu (reading hin) -> y in smem
//  phase 2: GEMM (y smem-resident, W double-buffered per kb=32 chunk)
//  phase 3: LN2+gelu + residual(hin) -> hout   (ping-pong: no intra-launch race)
// smem: Wbuf float2[2][16*193] + ysf float[32*194] = 74240 B, 3 blocks/SM
// ---------------------------------------------------------------------------
__global__ __launch_bounds__(128, 3) void fused_layer_kernel(
    const float* __restrict__ hin, float* __restrict__ hout,
    const float* __restrict__ W,  const float* __restrict__ bias,
    const float* __restrict__ g2, const float* __restrict__ b2,
    const float* __restrict__ sw, const float* __restrict__ sb,
    const float* __restrict__ g1, const float* __restrict__ b1,
    const float* __restrict__ mask, const float* __restrict__ x,
    const float* __restrict__ prew, const float* __restrict__ preb,
    int d, int first)
{
    extern __shared__ float sm[];
    float2* Wb  = (float2*)sm;            // [2][16*193] float2
    float*  ysf = sm + 2*16*193*2;        // [32][194] float
    int tid = threadIdx.x, lane = tid & 31, w = tid >> 5;
    int m0 = blockIdx.x * 32;

    // ---- prologue: fill W buffer 0 (kb=0): 192 co x 8 float4 = 1536 loads ----
    #pragma unroll
    for (int i = 0; i < 12; i++) {
        int idx = tid + i*128;            // 0..1535
        int co = idx >> 3, q = idx & 7;
        float4 v = *reinterpret_cast<const float4*>(W + co*192 + q*4);
        Wb[(q*2  )*193 + co] = make_float2(v.x, v.y);
        Wb[(q*2+1)*193 + co] = make_float2(v.z, v.w);
    }

    // ---- dw + LN1 + gelu into ysf ----
    for (int r = 0; r < 8; r++) {
        int row = w*8 + r;
        int pos = m0 + row;
        int t = pos & 4095;
        float mC = mask[pos];
        bool hasL = (t >= d), hasR = (t + d < TLEN);
        float mL = hasL ? mask[pos-d] : 0.f;
        float mR = hasR ? mask[pos+d] : 0.f;
        const float* hrow = hin + (size_t)pos*C;
        float x0C=0.f, x0L=0.f, x0R=0.f;
        if (first) {
            const float* xr = x + (size_t)(pos >> 12)*2*TLEN;
            x0C = xr[t];
            if (hasL) x0L = xr[t-d];
            if (hasR) x0R = xr[t+d];
        }
        float v[6]; float s1 = 0.f;
        #pragma unroll
        for (int k=0;k<6;k++) {
            int c = lane + 32*k;
            float hC, hL = 0.f, hR = 0.f;
            if (first) {
                float pw = prew[c], pb = preb[c];
                hC = fmaf(pw, x0C, pb);
                if (hasL) hL = fmaf(pw, x0L, pb);
                if (hasR) hR = fmaf(pw, x0R, pb);
            } else {
                hC = hrow[c];
                if (hasL) hL = hrow[c - d*C];
                if (hasR) hR = hrow[c + d*C];
            }
            float y = sb[c];
            y = fmaf(sw[c*3+1], hC*mC, y);
            if (hasL) y = fmaf(sw[c*3+0], hL*mL, y);
            if (hasR) y = fmaf(sw[c*3+2], hR*mR, y);
            v[k] = y; s1 += y;
        }
        #pragma unroll
        for (int o=16;o;o>>=1) s1 += __shfl_xor_sync(0xffffffffu, s1, o);
        float mean = s1*(1.f/192.f);
        float s2 = 0.f;
        #pragma unroll
        for (int k=0;k<6;k++){ float e = v[k]-mean; s2 += e*e; }
        #pragma unroll
        for (int o=16;o;o>>=1) s2 += __shfl_xor_sync(0xffffffffu, s2, o);
        float inv = rsqrtf(s2*(1.f/192.f) + 1e-5f);
        #pragma unroll
        for (int k=0;k<6;k++){
            int c = lane + 32*k;
            float u = fmaf(g1[c], (v[k]-mean)*inv, b1[c]);
            ysf[row*194 + c] = geluf(u);
        }
    }
    __syncthreads();

    // ---- GEMM: acc[r][j] over K=192, W streamed in 6 chunks of 32 ----
    unsigned long long acc[8][6];
    #pragma unroll
    for (int r=0;r<8;r++)
        #pragma unroll
        for (int j=0;j<6;j++) acc[r][j] = 0ull;

    #pragma unroll 1
    for (int kb = 0; kb < 6; kb++) {
        const float2* wb = Wb + (kb & 1)*(16*193);
        if (kb < 5) {
            float2* wn = Wb + ((kb+1) & 1)*(16*193);
            #pragma unroll
            for (int i = 0; i < 12; i++) {
                int idx = tid + i*128;       // 0..1535
                int co = idx >> 3, q = idx & 7;
                float4 v = *reinterpret_cast<const float4*>(W + co*192 + (kb+1)*32 + q*4);
                wn[(q*2  )*193 + co] = make_float2(v.x, v.y);
                wn[(q*2+1)*193 + co] = make_float2(v.z, v.w);
            }
        }
        const float* ybase = ysf + (w*8)*194 + kb*32;
        unsigned long long bA[6], bB[6], a8[8];
        #pragma unroll
        for (int j=0;j<6;j++)
            bA[j] = *reinterpret_cast<const unsigned long long*>(&wb[lane + 32*j]);
        #pragma unroll
        for (int c2 = 0; c2 < 16; c2 += 2) {
            #pragma unroll
            for (int r=0;r<8;r++)
                a8[r] = *reinterpret_cast<const unsigned long long*>(ybase + r*194 + 2*c2);
            #pragma unroll
            for (int j=0;j<6;j++)
                bB[j] = *reinterpret_cast<const unsigned long long*>(&wb[(c2+1)*193 + lane + 32*j]);
            #pragma unroll
            for (int j=0;j<6;j++)
                #pragma unroll
                for (int r=0;r<8;r++)
                    asm("fma.rn.f32x2 %0, %1, %2, %0;"
                        : "+l"(acc[r][j]) : "l"(a8[r]), "l"(bA[j]));
            #pragma unroll
            for (int r=0;r<8;r++)
                a8[r] = *reinterpret_cast<const unsigned long long*>(ybase + r*194 + 2*(c2+1));
            if (c2 + 2 < 16) {
                #pragma unroll
                for (int j=0;j<6;j++)
                    bA[j] = *reinterpret_cast<const unsigned long long*>(&wb[(c2+2)*193 + lane + 32*j]);
            }
            #pragma unroll
            for (int j=0;j<6;j++)
                #pragma unroll
                for (int r=0;r<8;r++)
                    asm("fma.rn.f32x2 %0, %1, %2, %0;"
                        : "+l"(acc[r][j]) : "l"(a8[r]), "l"(bB[j]));
        }
        __syncthreads();
    }

    // ---- epilogue: LN2 + gelu + residual(hin) -> hout ----
    #pragma unroll
    for (int r=0;r<8;r++){
        int row = w*8 + r;
        int pos = m0 + row;
        float vv[6]; float s1 = 0.f;
        #pragma unroll
        for (int j=0;j<6;j++){
            int co = lane+32*j;
            unsigned long long a = acc[r][j];
            float lo = __uint_as_float((unsigned)(a & 0xffffffffu));
            float hi = __uint_as_float((unsigned)(a >> 32));
            float vx = lo + hi + bias[co];
            vv[j] = vx; s1 += vx;
        }
        #pragma unroll
        for (int o=16;o;o>>=1) s1 += __shfl_xor_sync(0xffffffffu, s1, o);
        float mean = s1*(1.f/192.f);
        float s2 = 0.f;
        #pragma unroll
        for (int j=0;j<6;j++){ float e = vv[j]-mean; s2 += e*e; }
        #pragma unroll
        for (int o=16;o;o>>=1) s2 += __shfl_xor_sync(0xffffffffu, s2, o);
        float inv = rsqrtf(s2*(1.f/192.f) + 1e-5f);
        size_t rowo = (size_t)pos*C;
        float x0v = 0.f;
        if (first) x0v = x[(size_t)(pos >> 12)*2*TLEN + (pos & 4095)];
        #pragma unroll
        for (int j=0;j<6;j++){
            int co = lane+32*j;
            float u = fmaf(g2[co], (vv[j]-mean)*inv, b2[co]);
            float base = first ? fmaf(prew[co], x0v, preb[co]) : hin[rowo+co];
            hout[rowo+co] = base + geluf(u);
        }
    }
}

// ---------------------------------------------------------------------------
// p[pos, j] = (mask * sum_ci Wp[j,ci]*h[pos,ci] + bp[j]) * mask, j<29
// ---------------------------------------------------------------------------
__global__ __launch_bounds__(256) void proj_kernel(
    const float* __restrict__ h,
    const float* __restrict__ Wp, const float* __restrict__ bp,
    const float* __restrict__ mask)
{
    int warp = threadIdx.x >> 5, lane = threadIdx.x & 31;
    int pos = blockIdx.x*8 + warp;
    float m = mask[pos];
    const float* hrow = h + (size_t)pos*C;
    float hv[6];
    #pragma unroll
    for (int k=0;k<6;k++) hv[k] = hrow[lane+32*k];
    float acc[29];
    #pragma unroll
    for (int j=0;j<29;j++) acc[j]=0.f;
    #pragma unroll
    for (int k=0;k<6;k++){
        int c = lane+32*k;
        #pragma unroll
        for (int j=0;j<29;j++)
            acc[j] = fmaf(Wp[j*192+c], hv[k], acc[j]);
    }
    #pragma unroll
    for (int o=16;o;o>>=1){
        #pragma unroll
        for (int j=0;j<29;j++) acc[j] += __shfl_xor_sync(0xffffffffu, acc[j], o);
    }
    float sel = 0.f;
    #pragma unroll
    for (int j=0;j<29;j++) if (lane==j) sel = acc[j];
    if (lane < 29)
        g_p[(size_t)pos*32 + lane] = fmaf(m, sel, bp[lane]) * m;
}

// ---------------------------------------------------------------------------
// rational-quadratic spline
// ---------------------------------------------------------------------------
__global__ __launch_bounds__(256) void spline_kernel(
    const float* __restrict__ x, const float* __restrict__ mask,
    float* __restrict__ out)
{
    int pos = blockIdx.x*256 + threadIdx.x;
    int b = pos >> 12, t = pos & 4095;
    float m = mask[pos];
    const float* p = g_p + (size_t)pos*32;
    const float SCALE = 13.856406460551018f; // sqrt(192)

    float x0v = x[(size_t)b*2*TLEN + t];
    float x1v = x[(size_t)b*2*TLEN + TLEN + t];

    float cw[11], wd[10];
    {
        float u[10]; float mx = -1e30f;
        #pragma unroll
        for (int k=0;k<10;k++){ u[k] = p[k]/SCALE; mx = fmaxf(mx,u[k]); }
        float s=0.f; float e[10];
        #pragma unroll
        for (int k=0;k<10;k++){ e[k]=expf(u[k]-mx); s+=e[k]; }
        float run=0.f; cw[0]=-5.f;
        #pragma unroll
        for (int k=0;k<10;k++){ run += 0.001f + 0.99f*(e[k]/s); cw[k+1] = 10.f*run - 5.f; }
        cw[10] = 5.f;
        #pragma unroll
        for (int k=0;k<10;k++) wd[k] = cw[k+1]-cw[k];
    }
    float ch[11], hg[10];
    {
        float u[10]; float mx = -1e30f;
        #pragma unroll
        for (int k=0;k<10;k++){ u[k] = p[10+k]/SCALE; mx = fmaxf(mx,u[k]); }
        float s=0.f; float e[10];
        #pragma unroll
        for (int k=0;k<10;k++){ e[k]=expf(u[k]-mx); s+=e[k]; }
        float run=0.f; ch[0]=-5.f;
        #pragma unroll
        for (int k=0;k<10;k++){ run += 0.001f + 0.99f*(e[k]/s); ch[k+1] = 10.f*run - 5.f; }
        ch[10] = 5.f;
        #pragma unroll
        for (int k=0;k<10;k++) hg[k] = ch[k+1]-ch[k];
    }
    float dv[11];
    dv[0] = 1.0f; dv[10] = 1.0f;
    #pragma unroll
    for (int k=0;k<9;k++){
        float q = p[20+k];
        float sp = (q > 20.f) ? q : log1pf(expf(q));
        dv[k+1] = 0.001f + sp;
    }
    float xin = fminf(fmaxf(x1v, -5.f), 5.f);
    int cnt = 0;
    #pragma unroll
    for (int k=0;k<10;k++) cnt += (xin >= cw[k]) ? 1 : 0;
    int bin = cnt-1; if (bin < 0) bin = 0; if (bin > 9) bin = 9;

    float icw=cw[bin], iw=wd[bin], ich=ch[bin], ih=hg[bin];
    float dl=dv[bin], dr=dv[bin+1];
    float delta = ih/iw;
    float th  = (xin - icw)/iw;
    float t1m = th*(1.f-th);
    float num = ih*(delta*th*th + dl*t1m);
    float den = delta + (dl+dr-2.f*delta)*t1m;
    float yv  = ich + num/den;
    float onem = 1.f-th;
    float dnum = delta*delta*(dr*th*th + 2.f*delta*t1m + dl*onem*onem);
    float lad  = logf(dnum) - 2.f*logf(den);
    bool inside = (x1v >= -5.f) && (x1v <= 5.f);
    float xo   = inside ? yv  : x1v;
    float ladv = inside ? lad : 0.f;

    out[(size_t)b*2*TLEN + t]        = x0v * m;
    out[(size_t)b*2*TLEN + TLEN + t] = xo  * m;
    g_lad[pos] = ladv * m;
}

// ---------------------------------------------------------------------------
// deterministic per-batch logdet reduction
// ---------------------------------------------------------------------------
__global__ void logdet_kernel(float* __restrict__ out) {
    int b = blockIdx.x, tid = threadIdx.x;
    float s = 0.f;
    #pragma unroll
    for (int k=0;k<16;k++) s += g_lad[b*TLEN + k*256 + tid];
    __shared__ float smr[256];
    smr[tid] = s; __syncthreads();
    #pragma unroll
    for (int o=128;o;o>>=1){ if (tid<o) smr[tid]+=smr[tid+o]; __syncthreads(); }
    if (tid==0) out[b] = smr[0];
}

extern "C" void kernel_launch(void* const* d_in, const int* in_sizes, int n_in,
                              void* d_out, int out_size) {
    const float* x      = (const float*)d_in[0];
    const float* mask   = (const float*)d_in[1];
    const float* pre_w  = (const float*)d_in[2];
    const float* pre_b  = (const float*)d_in[3];
    const float* sep_w  = (const float*)d_in[4];
    const float* sep_b  = (const float*)d_in[5];
    const float* pw_w   = (const float*)d_in[6];
    const float* pw_b   = (const float*)d_in[7];
    const float* ln1_g  = (const float*)d_in[8];
    const float* ln1_b  = (const float*)d_in[9];
    const float* ln2_g  = (const float*)d_in[10];
    const float* ln2_b  = (const float*)d_in[11];
    const float* proj_w = (const float*)d_in[12];
    const float* proj_b = (const float*)d_in[13];
    float* out = (float*)d_out;

    float* hbuf[2];
    cudaGetSymbolAddress((void**)&hbuf[0], g_h0);
    cudaGetSymbolAddress((void**)&hbuf[1], g_h1);

    const int SMEM = (2*16*193*2 + 32*194) * 4;   // 74240 B
    cudaFuncSetAttribute(fused_layer_kernel,
                         cudaFuncAttributeMaxDynamicSharedMemorySize, SMEM);

    // layer0: x -> buf0 ; layer1: buf0 -> buf1 ; layer2: buf1 -> buf0
    int d = 1;
    for (int i = 0; i < 3; i++) {
        int first = (i == 0);
        const float* hin = hbuf[(i+1) & 1];
        float* hout      = hbuf[i & 1];
        fused_layer_kernel<<<BT/32, 128, SMEM>>>(
            hin, hout,
            pw_w + (size_t)i*C*C, pw_b + (size_t)i*C,
            ln2_g + (size_t)i*C, ln2_b + (size_t)i*C,
            sep_w + (size_t)i*C*3, sep_b + (size_t)i*C,
            ln1_g + (size_t)i*C, ln1_b + (size_t)i*C,
            mask, x, pre_w, pre_b, d, first);
        d *= 3;
    }

    proj_kernel<<<BT/8, 256>>>(hbuf[0], proj_w, proj_b, mask);
    spline_kernel<<<BT/256, 256>>>(x, mask, out);
    logdet_kernel<<<64, 256>>>(out + (size_t)BATCH*2*TLEN);
}

// round 7
// speedup vs baseline: 1.4677x; 1.4677x over previous
#include <cuda_runtime.h>
#include <math.h>
#include <stdint.h>

#define BATCH 64
#define TLEN  4096
#define BT    (BATCH*TLEN)
#define C     192

__device__ float g_h0[(size_t)BT*C];
__device__ float g_h1[(size_t)BT*C];
__device__ float g_p[(size_t)BT*32];
__device__ float g_lad[BT];

__device__ __forceinline__ float geluf(float u) {
    return 0.5f*u*(1.f + erff(u*0.7071067811865475f));
}
__device__ __forceinline__ uint32_t f2tf32(float f) {
    uint32_t r; asm("cvt.rna.tf32.f32 %0, %1;" : "=r"(r) : "f"(f)); return r;
}
__device__ __forceinline__ void mma_tf32(float* d, uint32_t a0, uint32_t a1,
                                         uint32_t a2, uint32_t a3,
                                         uint32_t b0, uint32_t b1) {
    asm volatile("mma.sync.aligned.m16n8k8.row.col.f32.tf32.tf32.f32 "
        "{%0,%1,%2,%3}, {%4,%5,%6,%7}, {%8,%9}, {%0,%1,%2,%3};"
        : "+f"(d[0]), "+f"(d[1]), "+f"(d[2]), "+f"(d[3])
        : "r"(a0), "r"(a1), "r"(a2), "r"(a3), "r"(b0), "r"(b1));
}

// smem layout (bytes)
#define OFF_YS   0                  // u32 tf32 / later fp32: [64][196]
#define OFF_W    50176              // u32 tf32: [2][192][36]
#define OFF_PS1  105472             // float [2][64]
#define OFF_PS2  105984             // float [2][64]
#define SMEM_FL  106496

// ---------------------------------------------------------------------------
// Fused layer: 64 positions/block, 256 threads (8 warps: 4 M-groups x 2 N-groups)
// dw+LN1+gelu -> ys(tf32) ; mma.sync tf32 GEMM (W double-buffered) ;
// LN2+gelu -> ys(fp32) ; coalesced residual+store (ping-pong buffers)
// ---------------------------------------------------------------------------
__global__ __launch_bounds__(256, 2) void fused_layer_mma(
    const float* __restrict__ hin, float* __restrict__ hout,
    const float* __restrict__ W,  const float* __restrict__ bias,
    const float* __restrict__ g2, const float* __restrict__ b2,
    const float* __restrict__ sw, const float* __restrict__ sb,
    const float* __restrict__ g1, const float* __restrict__ b1,
    const float* __restrict__ mask, const float* __restrict__ x,
    const float* __restrict__ prew, const float* __restrict__ preb,
    int d, int first)
{
    extern __shared__ char smem[];
    uint32_t* ysu = (uint32_t*)(smem + OFF_YS);   // [64][196] tf32
    float*    ysf = (float*)(smem + OFF_YS);      // same storage, fp32 in epilogue
    uint32_t* Wc  = (uint32_t*)(smem + OFF_W);    // [2][192][36]
    float*    ps1 = (float*)(smem + OFF_PS1);     // [2][64]
    float*    ps2 = (float*)(smem + OFF_PS2);     // [2][64]
    int tid = threadIdx.x, lane = tid & 31, w = tid >> 5;
    int m0 = blockIdx.x * 64;

    // ---- fill W chunk 0 (tf32) ----
    {
        uint32_t* b0 = Wc;
        #pragma unroll
        for (int i = 0; i < 6; i++) {
            int idx = tid + i*256;            // 0..1535 = 192co x 8 float4
            int co = idx >> 3, q = idx & 7;
            float4 v = *reinterpret_cast<const float4*>(W + co*192 + q*4);
            uint4 tv = make_uint4(f2tf32(v.x), f2tf32(v.y), f2tf32(v.z), f2tf32(v.w));
            *reinterpret_cast<uint4*>(b0 + co*36 + q*4) = tv;
        }
    }

    // ---- dw + LN1 + gelu -> ys (tf32). warp w: rows w*8..w*8+7 ----
    for (int r = 0; r < 8; r++) {
        int row = w*8 + r;
        int pos = m0 + row;
        int t = pos & 4095;
        float mC = mask[pos];
        bool hasL = (t >= d), hasR = (t + d < TLEN);
        float mL = hasL ? mask[pos-d] : 0.f;
        float mR = hasR ? mask[pos+d] : 0.f;
        const float* hrow = hin + (size_t)pos*C;
        float x0C=0.f, x0L=0.f, x0R=0.f;
        if (first) {
            const float* xr = x + (size_t)(pos >> 12)*2*TLEN;
            x0C = xr[t];
            if (hasL) x0L = xr[t-d];
            if (hasR) x0R = xr[t+d];
        }
        float v[6]; float s1 = 0.f;
        #pragma unroll
        for (int k = 0; k < 6; k++) {
            int c = lane + 32*k;
            float hC, hL = 0.f, hR = 0.f;
            if (first) {
                float pw = prew[c], pb = preb[c];
                hC = fmaf(pw, x0C, pb);
                if (hasL) hL = fmaf(pw, x0L, pb);
                if (hasR) hR = fmaf(pw, x0R, pb);
            } else {
                hC = hrow[c];
                if (hasL) hL = hrow[c - d*C];
                if (hasR) hR = hrow[c + d*C];
            }
            float y = sb[c];
            y = fmaf(sw[c*3+1], hC*mC, y);
            if (hasL) y = fmaf(sw[c*3+0], hL*mL, y);
            if (hasR) y = fmaf(sw[c*3+2], hR*mR, y);
            v[k] = y; s1 += y;
        }
        #pragma unroll
        for (int o=16;o;o>>=1) s1 += __shfl_xor_sync(0xffffffffu, s1, o);
        float mean = s1*(1.f/192.f);
        float s2 = 0.f;
        #pragma unroll
        for (int k=0;k<6;k++){ float e = v[k]-mean; s2 += e*e; }
        #pragma unroll
        for (int o=16;o;o>>=1) s2 += __shfl_xor_sync(0xffffffffu, s2, o);
        float inv = rsqrtf(s2*(1.f/192.f) + 1e-5f);
        #pragma unroll
        for (int k=0;k<6;k++){
            int c = lane + 32*k;
            float u = fmaf(g1[c], (v[k]-mean)*inv, b1[c]);
            ysu[row*196 + c] = f2tf32(geluf(u));
        }
    }
    __syncthreads();

    // ---- GEMM: warp (mw, nw) computes rows mw*16..+15, cols nw*96..+95 ----
    int mw = w & 3, nw = w >> 2;
    int gr = lane >> 2, kq = lane & 3;           // groupID, thread-in-group
    float acc[12][4];
    #pragma unroll
    for (int nf=0;nf<12;nf++)
        #pragma unroll
        for (int i=0;i<4;i++) acc[nf][i] = 0.f;

    #pragma unroll 1
    for (int kb = 0; kb < 6; kb++) {
        if (kb < 5) {
            uint32_t* bn = Wc + ((kb+1) & 1)*192*36;
            #pragma unroll
            for (int i = 0; i < 6; i++) {
                int idx = tid + i*256;
                int co = idx >> 3, q = idx & 7;
                float4 v = *reinterpret_cast<const float4*>(W + co*192 + (kb+1)*32 + q*4);
                uint4 tv = make_uint4(f2tf32(v.x), f2tf32(v.y), f2tf32(v.z), f2tf32(v.w));
                *reinterpret_cast<uint4*>(bn + co*36 + q*4) = tv;
            }
        }
        const uint32_t* wb = Wc + (kb & 1)*192*36;
        #pragma unroll
        for (int k4 = 0; k4 < 4; k4++) {
            int kc = kb*32 + k4*8 + kq;
            uint32_t a0 = ysu[(mw*16 + gr    )*196 + kc    ];
            uint32_t a1 = ysu[(mw*16 + gr + 8)*196 + kc    ];
            uint32_t a2 = ysu[(mw*16 + gr    )*196 + kc + 4];
            uint32_t a3 = ysu[(mw*16 + gr + 8)*196 + kc + 4];
            #pragma unroll
            for (int nf = 0; nf < 12; nf++) {
                int col = nw*96 + nf*8 + gr;
                uint32_t b0 = wb[col*36 + k4*8 + kq    ];
                uint32_t b1 = wb[col*36 + k4*8 + kq + 4];
                mma_tf32(acc[nf], a0, a1, a2, a3, b0, b1);
            }
        }
        __syncthreads();
    }

    // ---- epilogue: bias, LN2 (quad shuffle + smem combine), gelu -> ysf ----
    {
        float s1r0=0.f, s2r0=0.f, s1r1=0.f, s2r1=0.f;
        #pragma unroll
        for (int nf = 0; nf < 12; nf++) {
            int c0 = nw*96 + nf*8 + kq*2;
            float bv0 = bias[c0], bv1 = bias[c0+1];
            acc[nf][0] += bv0; acc[nf][1] += bv1;
            acc[nf][2] += bv0; acc[nf][3] += bv1;
            s1r0 += acc[nf][0] + acc[nf][1];
            s2r0 += acc[nf][0]*acc[nf][0] + acc[nf][1]*acc[nf][1];
            s1r1 += acc[nf][2] + acc[nf][3];
            s2r1 += acc[nf][2]*acc[nf][2] + acc[nf][3]*acc[nf][3];
        }
        #pragma unroll
        for (int o = 1; o <= 2; o <<= 1) {
            s1r0 += __shfl_xor_sync(0xffffffffu, s1r0, o);
            s2r0 += __shfl_xor_sync(0xffffffffu, s2r0, o);
            s1r1 += __shfl_xor_sync(0xffffffffu, s1r1, o);
            s2r1 += __shfl_xor_sync(0xffffffffu, s2r1, o);
        }
        int row0 = mw*16 + gr, row1 = row0 + 8;
        if (kq == 0) {
            ps1[nw*64 + row0] = s1r0; ps2[nw*64 + row0] = s2r0;
            ps1[nw*64 + row1] = s1r1; ps2[nw*64 + row1] = s2r1;
        }
        __syncthreads();
        float S10 = ps1[row0] + ps1[64 + row0];
        float S20 = ps2[row0] + ps2[64 + row0];
        float S11 = ps1[row1] + ps1[64 + row1];
        float S21 = ps2[row1] + ps2[64 + row1];
        float mean0 = S10*(1.f/192.f);
        float inv0  = rsqrtf(S20*(1.f/192.f) - mean0*mean0 + 1e-5f);
        float mean1 = S11*(1.f/192.f);
        float inv1  = rsqrtf(S21*(1.f/192.f) - mean1*mean1 + 1e-5f);
        __syncthreads();   // ysu reads done by all warps before overwrite
        #pragma unroll
        for (int nf = 0; nf < 12; nf++) {
            int c0 = nw*96 + nf*8 + kq*2;
            float ga = g2[c0], gb = g2[c0+1], ba = b2[c0], bb = b2[c0+1];
            ysf[row0*196 + c0    ] = geluf(fmaf(ga, (acc[nf][0]-mean0)*inv0, ba));
            ysf[row0*196 + c0 + 1] = geluf(fmaf(gb, (acc[nf][1]-mean0)*inv0, bb));
            ysf[row1*196 + c0    ] = geluf(fmaf(ga, (acc[nf][2]-mean1)*inv1, ba));
            ysf[row1*196 + c0 + 1] = geluf(fmaf(gb, (acc[nf][3]-mean1)*inv1, bb));
        }
    }
    __syncthreads();

    // ---- coalesced residual + store ----
    for (int r = 0; r < 8; r++) {
        int row = w*8 + r;
        int pos = m0 + row;
        size_t rowo = (size_t)pos*C;
        float x0v = 0.f;
        if (first) x0v = x[(size_t)(pos >> 12)*2*TLEN + (pos & 4095)];
        #pragma unroll
        for (int k = 0; k < 6; k++) {
            int c = lane + 32*k;
            float base = first ? fmaf(prew[c], x0v, preb[c]) : hin[rowo + c];
            hout[rowo + c] = base + ysf[row*196 + c];
        }
    }
}

// ---------------------------------------------------------------------------
// proj: block = 64 positions, 128 threads; Wp + h rows in smem.
// thread t: position t>>1, outputs [15*(t&1) .. +15/14)
// ---------------------------------------------------------------------------
__global__ __launch_bounds__(128) void proj_kernel(
    const float* __restrict__ h,
    const float* __restrict__ Wp, const float* __restrict__ bp,
    const float* __restrict__ mask)
{
    extern __shared__ float psm[];
    float* wps = psm;               // [29][192]
    float* hs  = psm + 29*192;      // [64][196]
    int tid = threadIdx.x;
    int m0 = blockIdx.x * 64;

    for (int i = tid; i < 29*192; i += 128) wps[i] = Wp[i];
    #pragma unroll
    for (int i = 0; i < 24; i++) {
        int i4 = tid + i*128;                 // 0..3071 float4
        int row = i4 / 48, q = i4 % 48;
        float4 v = *reinterpret_cast<const float4*>(h + (size_t)(m0+row)*C + q*4);
        *reinterpret_cast<float4*>(hs + row*196 + q*4) = v;
    }
    __syncthreads();

    int p = tid >> 1, jh = tid & 1;
    int j0 = jh ? 15 : 0, nj = jh ? 14 : 15;
    float acc[15];
    #pragma unroll
    for (int j = 0; j < 15; j++) acc[j] = 0.f;
    const float* hrow = hs + p*196;
    for (int c = 0; c < 192; c++) {
        float hv = hrow[c];
        #pragma unroll
        for (int j = 0; j < 15; j++)
            if (j < nj) acc[j] = fmaf(wps[(j0+j)*192 + c], hv, acc[j]);
    }
    int pos = m0 + p;
    float m = mask[pos];
    for (int j = 0; j < nj; j++)
        g_p[(size_t)pos*32 + j0 + j] = fmaf(m, acc[j], bp[j0+j]) * m;
}

// ---------------------------------------------------------------------------
// rational-quadratic spline
// ---------------------------------------------------------------------------
__global__ __launch_bounds__(256) void spline_kernel(
    const float* __restrict__ x, const float* __restrict__ mask,
    float* __restrict__ out)
{
    int pos = blockIdx.x*256 + threadIdx.x;
    int b = pos >> 12, t = pos & 4095;
    float m = mask[pos];
    const float* p = g_p + (size_t)pos*32;
    const float SCALE = 13.856406460551018f;

    float x0v = x[(size_t)b*2*TLEN + t];
    float x1v = x[(size_t)b*2*TLEN + TLEN + t];

    float cw[11], wd[10];
    {
        float u[10]; float mx = -1e30f;
        #pragma unroll
        for (int k=0;k<10;k++){ u[k] = p[k]/SCALE; mx = fmaxf(mx,u[k]); }
        float s=0.f; float e[10];
        #pragma unroll
        for (int k=0;k<10;k++){ e[k]=expf(u[k]-mx); s+=e[k]; }
        float run=0.f; cw[0]=-5.f;
        #pragma unroll
        for (int k=0;k<10;k++){ run += 0.001f + 0.99f*(e[k]/s); cw[k+1] = 10.f*run - 5.f; }
        cw[10] = 5.f;
        #pragma unroll
        for (int k=0;k<10;k++) wd[k] = cw[k+1]-cw[k];
    }
    float ch[11], hg[10];
    {
        float u[10]; float mx = -1e30f;
        #pragma unroll
        for (int k=0;k<10;k++){ u[k] = p[10+k]/SCALE; mx = fmaxf(mx,u[k]); }
        float s=0.f; float e[10];
        #pragma unroll
        for (int k=0;k<10;k++){ e[k]=expf(u[k]-mx); s+=e[k]; }
        float run=0.f; ch[0]=-5.f;
        #pragma unroll
        for (int k=0;k<10;k++){ run += 0.001f + 0.99f*(e[k]/s); ch[k+1] = 10.f*run - 5.f; }
        ch[10] = 5.f;
        #pragma unroll
        for (int k=0;k<10;k++) hg[k] = ch[k+1]-ch[k];
    }
    float dv[11];
    dv[0] = 1.0f; dv[10] = 1.0f;
    #pragma unroll
    for (int k=0;k<9;k++){
        float q = p[20+k];
        float sp = (q > 20.f) ? q : log1pf(expf(q));
        dv[k+1] = 0.001f + sp;
    }
    float xin = fminf(fmaxf(x1v, -5.f), 5.f);
    int cnt = 0;
    #pragma unroll
    for (int k=0;k<10;k++) cnt += (xin >= cw[k]) ? 1 : 0;
    int bin = cnt-1; if (bin < 0) bin = 0; if (bin > 9) bin = 9;

    float icw=cw[bin], iw=wd[bin], ich=ch[bin], ih=hg[bin];
    float dl=dv[bin], dr=dv[bin+1];
    float delta = ih/iw;
    float th  = (xin - icw)/iw;
    float t1m = th*(1.f-th);
    float num = ih*(delta*th*th + dl*t1m);
    float den = delta + (dl+dr-2.f*delta)*t1m;
    float yv  = ich + num/den;
    float onem = 1.f-th;
    float dnum = delta*delta*(dr*th*th + 2.f*delta*t1m + dl*onem*onem);
    float lad  = logf(dnum) - 2.f*logf(den);
    bool inside = (x1v >= -5.f) && (x1v <= 5.f);
    float xo   = inside ? yv  : x1v;
    float ladv = inside ? lad : 0.f;

    out[(size_t)b*2*TLEN + t]        = x0v * m;
    out[(size_t)b*2*TLEN + TLEN + t] = xo  * m;
    g_lad[pos] = ladv * m;
}

__global__ void logdet_kernel(float* __restrict__ out) {
    int b = blockIdx.x, tid = threadIdx.x;
    float s = 0.f;
    #pragma unroll
    for (int k=0;k<16;k++) s += g_lad[b*TLEN + k*256 + tid];
    __shared__ float smr[256];
    smr[tid] = s; __syncthreads();
    #pragma unroll
    for (int o=128;o;o>>=1){ if (tid<o) smr[tid]+=smr[tid+o]; __syncthreads(); }
    if (tid==0) out[b] = smr[0];
}

extern "C" void kernel_launch(void* const* d_in, const int* in_sizes, int n_in,
                              void* d_out, int out_size) {
    const float* x      = (const float*)d_in[0];
    const float* mask   = (const float*)d_in[1];
    const float* pre_w  = (const float*)d_in[2];
    const float* pre_b  = (const float*)d_in[3];
    const float* sep_w  = (const float*)d_in[4];
    const float* sep_b  = (const float*)d_in[5];
    const float* pw_w   = (const float*)d_in[6];
    const float* pw_b   = (const float*)d_in[7];
    const float* ln1_g  = (const float*)d_in[8];
    const float* ln1_b  = (const float*)d_in[9];
    const float* ln2_g  = (const float*)d_in[10];
    const float* ln2_b  = (const float*)d_in[11];
    const float* proj_w = (const float*)d_in[12];
    const float* proj_b = (const float*)d_in[13];
    float* out = (float*)d_out;

    float* hbuf[2];
    cudaGetSymbolAddress((void**)&hbuf[0], g_h0);
    cudaGetSymbolAddress((void**)&hbuf[1], g_h1);

    cudaFuncSetAttribute(fused_layer_mma,
                         cudaFuncAttributeMaxDynamicSharedMemorySize, SMEM_FL);
    const int PROJ_SMEM = (29*192 + 64*196) * 4;
    cudaFuncSetAttribute(proj_kernel,
                         cudaFuncAttributeMaxDynamicSharedMemorySize, PROJ_SMEM);

    int d = 1;
    for (int i = 0; i < 3; i++) {
        int first = (i == 0);
        const float* hin = hbuf[(i+1) & 1];
        float* hout      = hbuf[i & 1];
        fused_layer_mma<<<BT/64, 256, SMEM_FL>>>(
            hin, hout,
            pw_w + (size_t)i*C*C, pw_b + (size_t)i*C,
            ln2_g + (size_t)i*C, ln2_b + (size_t)i*C,
            sep_w + (size_t)i*C*3, sep_b + (size_t)i*C,
            ln1_g + (size_t)i*C, ln1_b + (size_t)i*C,
            mask, x, pre_w, pre_b, d, first);
        d *= 3;
    }

    proj_kernel<<<BT/64, 128, PROJ_SMEM>>>(hbuf[0], proj_w, proj_b, mask);
    spline_kernel<<<BT/256, 256>>>(x, mask, out);
    logdet_kernel<<<64, 256>>>(out + (size_t)BATCH*2*TLEN);
}

// round 8
// speedup vs baseline: 1.5709x; 1.0703x over previous
#include <cuda_runtime.h>
#include <math.h>
#include <stdint.h>

#define BATCH 64
#define TLEN  4096
#define BT    (BATCH*TLEN)
#define C     192

__device__ float g_h0[(size_t)BT*C];
__device__ float g_h1[(size_t)BT*C];
__device__ float g_p[(size_t)BT*32];
__device__ float g_lad[BT];

__device__ __forceinline__ float geluf(float u) {
    return 0.5f*u*(1.f + erff(u*0.7071067811865475f));
}
__device__ __forceinline__ uint32_t f2tf32(float f) {
    uint32_t r; asm("cvt.rna.tf32.f32 %0, %1;" : "=r"(r) : "f"(f)); return r;
}
// pack index: within each 8-wide k-group, (k, k+4) stored adjacently
__device__ __forceinline__ int pk(int c) {
    return (c & ~7) + ((c & 3) << 1) + ((c >> 2) & 1);
}
__device__ __forceinline__ void mma_tf32(float* d, uint32_t a0, uint32_t a1,
                                         uint32_t a2, uint32_t a3,
                                         uint32_t b0, uint32_t b1) {
    asm volatile("mma.sync.aligned.m16n8k8.row.col.f32.tf32.tf32.f32 "
        "{%0,%1,%2,%3}, {%4,%5,%6,%7}, {%8,%9}, {%0,%1,%2,%3};"
        : "+f"(d[0]), "+f"(d[1]), "+f"(d[2]), "+f"(d[3])
        : "r"(a0), "r"(a1), "r"(a2), "r"(a3), "r"(b0), "r"(b1));
}

// smem layout (bytes) for fused layer
#define OFF_YS   0                  // u32 tf32 (packed) / later fp32: [64][196]
#define OFF_W    50176              // u32 tf32 (packed): [2][192][36]
#define OFF_PS1  105472             // float [2][64]
#define OFF_PS2  105984             // float [2][64]
#define SMEM_FL  106496

// ---------------------------------------------------------------------------
// Fused layer: 64 positions/block, 256 threads (8 warps: 4 M x 2 N)
// ---------------------------------------------------------------------------
__global__ __launch_bounds__(256, 2) void fused_layer_mma(
    const float* __restrict__ hin, float* __restrict__ hout,
    const float* __restrict__ W,  const float* __restrict__ bias,
    const float* __restrict__ g2, const float* __restrict__ b2,
    const float* __restrict__ sw, const float* __restrict__ sb,
    const float* __restrict__ g1, const float* __restrict__ b1,
    const float* __restrict__ mask, const float* __restrict__ x,
    const float* __restrict__ prew, const float* __restrict__ preb,
    int d, int first)
{
    extern __shared__ char smem[];
    uint32_t* ysu = (uint32_t*)(smem + OFF_YS);   // [64][196] tf32 packed
    float*    ysf = (float*)(smem + OFF_YS);      // fp32 natural in epilogue
    uint32_t* Wc  = (uint32_t*)(smem + OFF_W);    // [2][192][36] packed
    float*    ps1 = (float*)(smem + OFF_PS1);
    float*    ps2 = (float*)(smem + OFF_PS2);
    int tid = threadIdx.x, lane = tid & 31, w = tid >> 5;
    int m0 = blockIdx.x * 64;

    // ---- fill W chunk 0 (tf32, pair-packed) ----
    {
        uint32_t* b0 = Wc;
        #pragma unroll
        for (int i = 0; i < 6; i++) {
            int idx = tid + i*256;            // 0..1535 = 192co x 8 float4
            int co = idx >> 3, q = idx & 7;
            float4 v = *reinterpret_cast<const float4*>(W + co*192 + q*4);
            uint32_t* dst = b0 + co*36 + (q>>1)*8 + (q&1);
            dst[0] = f2tf32(v.x); dst[2] = f2tf32(v.y);
            dst[4] = f2tf32(v.z); dst[6] = f2tf32(v.w);
        }
    }

    // ---- dw + LN1 + gelu -> ys (tf32 packed). warp w: rows w*8..w*8+7 ----
    for (int r = 0; r < 8; r++) {
        int row = w*8 + r;
        int pos = m0 + row;
        int t = pos & 4095;
        float mC = mask[pos];
        bool hasL = (t >= d), hasR = (t + d < TLEN);
        float mL = hasL ? mask[pos-d] : 0.f;
        float mR = hasR ? mask[pos+d] : 0.f;
        const float* hrow = hin + (size_t)pos*C;
        float x0C=0.f, x0L=0.f, x0R=0.f;
        if (first) {
            const float* xr = x + (size_t)(pos >> 12)*2*TLEN;
            x0C = xr[t];
            if (hasL) x0L = xr[t-d];
            if (hasR) x0R = xr[t+d];
        }
        float v[6]; float s1 = 0.f;
        #pragma unroll
        for (int k = 0; k < 6; k++) {
            int c = lane + 32*k;
            float hC, hL = 0.f, hR = 0.f;
            if (first) {
                float pw = prew[c], pb = preb[c];
                hC = fmaf(pw, x0C, pb);
                if (hasL) hL = fmaf(pw, x0L, pb);
                if (hasR) hR = fmaf(pw, x0R, pb);
            } else {
                hC = hrow[c];
                if (hasL) hL = hrow[c - d*C];
                if (hasR) hR = hrow[c + d*C];
            }
            float y = sb[c];
            y = fmaf(sw[c*3+1], hC*mC, y);
            if (hasL) y = fmaf(sw[c*3+0], hL*mL, y);
            if (hasR) y = fmaf(sw[c*3+2], hR*mR, y);
            v[k] = y; s1 += y;
        }
        #pragma unroll
        for (int o=16;o;o>>=1) s1 += __shfl_xor_sync(0xffffffffu, s1, o);
        float mean = s1*(1.f/192.f);
        float s2 = 0.f;
        #pragma unroll
        for (int k=0;k<6;k++){ float e = v[k]-mean; s2 += e*e; }
        #pragma unroll
        for (int o=16;o;o>>=1) s2 += __shfl_xor_sync(0xffffffffu, s2, o);
        float inv = rsqrtf(s2*(1.f/192.f) + 1e-5f);
        #pragma unroll
        for (int k=0;k<6;k++){
            int c = lane + 32*k;
            float u = fmaf(g1[c], (v[k]-mean)*inv, b1[c]);
            ysu[row*196 + pk(c)] = f2tf32(geluf(u));
        }
    }
    __syncthreads();

    // ---- GEMM: warp (mw, nw) -> rows mw*16..+15, cols nw*96..+95 ----
    int mw = w & 3, nw = w >> 2;
    int gr = lane >> 2, kq = lane & 3;
    float acc[12][4];
    #pragma unroll
    for (int nf=0;nf<12;nf++)
        #pragma unroll
        for (int i=0;i<4;i++) acc[nf][i] = 0.f;

    #pragma unroll 1
    for (int kb = 0; kb < 6; kb++) {
        if (kb < 5) {
            uint32_t* bn = Wc + ((kb+1) & 1)*192*36;
            #pragma unroll
            for (int i = 0; i < 6; i++) {
                int idx = tid + i*256;
                int co = idx >> 3, q = idx & 7;
                float4 v = *reinterpret_cast<const float4*>(W + co*192 + (kb+1)*32 + q*4);
                uint32_t* dst = bn + co*36 + (q>>1)*8 + (q&1);
                dst[0] = f2tf32(v.x); dst[2] = f2tf32(v.y);
                dst[4] = f2tf32(v.z); dst[6] = f2tf32(v.w);
            }
        }
        const uint32_t* wb = Wc + (kb & 1)*192*36;
        #pragma unroll
        for (int k4 = 0; k4 < 4; k4++) {
            int ko = kb*32 + k4*8 + kq*2;
            uint2 aP0 = *reinterpret_cast<const uint2*>(&ysu[(mw*16 + gr    )*196 + ko]);
            uint2 aP1 = *reinterpret_cast<const uint2*>(&ysu[(mw*16 + gr + 8)*196 + ko]);
            #pragma unroll
            for (int nf = 0; nf < 12; nf++) {
                int col = nw*96 + nf*8 + gr;
                uint2 bP = *reinterpret_cast<const uint2*>(&wb[col*36 + k4*8 + kq*2]);
                mma_tf32(acc[nf], aP0.x, aP1.x, aP0.y, aP1.y, bP.x, bP.y);
            }
        }
        __syncthreads();
    }

    // ---- epilogue: bias, LN2, gelu -> ysf ----
    {
        float s1r0=0.f, s2r0=0.f, s1r1=0.f, s2r1=0.f;
        #pragma unroll
        for (int nf = 0; nf < 12; nf++) {
            int c0 = nw*96 + nf*8 + kq*2;
            float bv0 = bias[c0], bv1 = bias[c0+1];
            acc[nf][0] += bv0; acc[nf][1] += bv1;
            acc[nf][2] += bv0; acc[nf][3] += bv1;
            s1r0 += acc[nf][0] + acc[nf][1];
            s2r0 += acc[nf][0]*acc[nf][0] + acc[nf][1]*acc[nf][1];
            s1r1 += acc[nf][2] + acc[nf][3];
            s2r1 += acc[nf][2]*acc[nf][2] + acc[nf][3]*acc[nf][3];
        }
        #pragma unroll
        for (int o = 1; o <= 2; o <<= 1) {
            s1r0 += __shfl_xor_sync(0xffffffffu, s1r0, o);
            s2r0 += __shfl_xor_sync(0xffffffffu, s2r0, o);
            s1r1 += __shfl_xor_sync(0xffffffffu, s1r1, o);
            s2r1 += __shfl_xor_sync(0xffffffffu, s2r1, o);
        }
        int row0 = mw*16 + gr, row1 = row0 + 8;
        if (kq == 0) {
            ps1[nw*64 + row0] = s1r0; ps2[nw*64 + row0] = s2r0;
            ps1[nw*64 + row1] = s1r1; ps2[nw*64 + row1] = s2r1;
        }
        __syncthreads();
        float S10 = ps1[row0] + ps1[64 + row0];
        float S20 = ps2[row0] + ps2[64 + row0];
        float S11 = ps1[row1] + ps1[64 + row1];
        float S21 = ps2[row1] + ps2[64 + row1];
        float mean0 = S10*(1.f/192.f);
        float inv0  = rsqrtf(S20*(1.f/192.f) - mean0*mean0 + 1e-5f);
        float mean1 = S11*(1.f/192.f);
        float inv1  = rsqrtf(S21*(1.f/192.f) - mean1*mean1 + 1e-5f);
        __syncthreads();
        #pragma unroll
        for (int nf = 0; nf < 12; nf++) {
            int c0 = nw*96 + nf*8 + kq*2;
            float ga = g2[c0], gb = g2[c0+1], ba = b2[c0], bb = b2[c0+1];
            ysf[row0*196 + c0    ] = geluf(fmaf(ga, (acc[nf][0]-mean0)*inv0, ba));
            ysf[row0*196 + c0 + 1] = geluf(fmaf(gb, (acc[nf][1]-mean0)*inv0, bb));
            ysf[row1*196 + c0    ] = geluf(fmaf(ga, (acc[nf][2]-mean1)*inv1, ba));
            ysf[row1*196 + c0 + 1] = geluf(fmaf(gb, (acc[nf][3]-mean1)*inv1, bb));
        }
    }
    __syncthreads();

    // ---- coalesced residual + store ----
    for (int r = 0; r < 8; r++) {
        int row = w*8 + r;
        int pos = m0 + row;
        size_t rowo = (size_t)pos*C;
        float x0v = 0.f;
        if (first) x0v = x[(size_t)(pos >> 12)*2*TLEN + (pos & 4095)];
        #pragma unroll
        for (int k = 0; k < 6; k++) {
            int c = lane + 32*k;
            float base = first ? fmaf(prew[c], x0v, preb[c]) : hin[rowo + c];
            hout[rowo + c] = base + ysf[row*196 + c];
        }
    }
}

// ---------------------------------------------------------------------------
// proj via mma: 32 positions/block, 128 threads (4 warps: 2 M x 2 K-split)
// M=32, N=32 (29 used), K=192. h + Wp tf32 pair-packed in smem.
// ---------------------------------------------------------------------------
#define PJ_HS   0                    // u32 [32][196]
#define PJ_WS   25088                // u32 [32][196]
#define PJ_PS   50176                // float [32][33]
#define PJ_SMEM 54400

__global__ __launch_bounds__(128) void proj_mma(
    const float* __restrict__ h,
    const float* __restrict__ Wp, const float* __restrict__ bp,
    const float* __restrict__ mask)
{
    extern __shared__ char smem[];
    uint32_t* hs  = (uint32_t*)(smem + PJ_HS);
    uint32_t* wps = (uint32_t*)(smem + PJ_WS);
    float*    ps  = (float*)(smem + PJ_PS);
    int tid = threadIdx.x, lane = tid & 31, w = tid >> 5;
    int m0 = blockIdx.x * 32;

    // zero pad cols 29..31 of Wp tile
    for (int i = tid; i < 3*196; i += 128) wps[29*196 + i] = 0;
    // Wp -> smem (tf32 packed): 29 rows x 48 float4
    for (int i4 = tid; i4 < 29*48; i4 += 128) {
        int j = i4 / 48, q = i4 % 48;           // q: float4 index within row
        float4 v = *reinterpret_cast<const float4*>(Wp + j*192 + q*4);
        int c = q*4;
        uint32_t* dst = wps + j*196;
        dst[pk(c  )] = f2tf32(v.x); dst[pk(c+1)] = f2tf32(v.y);
        dst[pk(c+2)] = f2tf32(v.z); dst[pk(c+3)] = f2tf32(v.w);
    }
    // h rows -> smem (tf32 packed): 32 rows x 48 float4
    #pragma unroll
    for (int i = 0; i < 12; i++) {
        int i4 = tid + i*128;                    // 0..1535
        int row = i4 / 48, q = i4 % 48;
        float4 v = *reinterpret_cast<const float4*>(h + (size_t)(m0+row)*C + q*4);
        int c = q*4;
        uint32_t* dst = hs + row*196;
        dst[pk(c  )] = f2tf32(v.x); dst[pk(c+1)] = f2tf32(v.y);
        dst[pk(c+2)] = f2tf32(v.z); dst[pk(c+3)] = f2tf32(v.w);
    }
    __syncthreads();

    int mw = w & 1, kw = w >> 1;
    int gr = lane >> 2, kq = lane & 3;
    float acc[4][4];
    #pragma unroll
    for (int nf=0;nf<4;nf++)
        #pragma unroll
        for (int i=0;i<4;i++) acc[nf][i] = 0.f;

    #pragma unroll
    for (int ks = 0; ks < 12; ks++) {
        int ko = kw*96 + ks*8 + kq*2;
        uint2 aP0 = *reinterpret_cast<const uint2*>(&hs[(mw*16 + gr    )*196 + ko]);
        uint2 aP1 = *reinterpret_cast<const uint2*>(&hs[(mw*16 + gr + 8)*196 + ko]);
        #pragma unroll
        for (int nf = 0; nf < 4; nf++) {
            uint2 bP = *reinterpret_cast<const uint2*>(&wps[(nf*8 + gr)*196 + ko]);
            mma_tf32(acc[nf], aP0.x, aP1.x, aP0.y, aP1.y, bP.x, bP.y);
        }
    }

    // K-combine: kw0 writes partials, kw1 adds + stores
    if (kw == 0) {
        #pragma unroll
        for (int nf = 0; nf < 4; nf++) {
            int j = nf*8 + kq*2;
            ps[(mw*16 + gr    )*33 + j    ] = acc[nf][0];
            ps[(mw*16 + gr    )*33 + j + 1] = acc[nf][1];
            ps[(mw*16 + gr + 8)*33 + j    ] = acc[nf][2];
            ps[(mw*16 + gr + 8)*33 + j + 1] = acc[nf][3];
        }
    }
    __syncthreads();
    if (kw == 1) {
        int row0 = mw*16 + gr, row1 = row0 + 8;
        float mA = mask[m0 + row0];
        float mB = mask[m0 + row1];
        float* gpA = g_p + (size_t)(m0 + row0)*32;
        float* gpB = g_p + (size_t)(m0 + row1)*32;
        #pragma unroll
        for (int nf = 0; nf < 4; nf++) {
            int j = nf*8 + kq*2;
            #pragma unroll
            for (int e = 0; e < 2; e++) {
                int jj = j + e;
                if (jj < 29) {
                    float bv = bp[jj];
                    gpA[jj] = fmaf(mA, acc[nf][e  ] + ps[row0*33 + jj], bv) * mA;
                    gpB[jj] = fmaf(mB, acc[nf][e+2] + ps[row1*33 + jj], bv) * mB;
                }
            }
        }
    }
}

// ---------------------------------------------------------------------------
// rational-quadratic spline
// ---------------------------------------------------------------------------
__global__ __launch_bounds__(256) void spline_kernel(
    const float* __restrict__ x, const float* __restrict__ mask,
    float* __restrict__ out)
{
    int pos = blockIdx.x*256 + threadIdx.x;
    int b = pos >> 12, t = pos & 4095;
    float m = mask[pos];
    const float* p = g_p + (size_t)pos*32;
    const float SCALE = 13.856406460551018f;

    float x0v = x[(size_t)b*2*TLEN + t];
    float x1v = x[(size_t)b*2*TLEN + TLEN + t];

    float cw[11], wd[10];
    {
        float u[10]; float mx = -1e30f;
        #pragma unroll
        for (int k=0;k<10;k++){ u[k] = p[k]/SCALE; mx = fmaxf(mx,u[k]); }
        float s=0.f; float e[10];
        #pragma unroll
        for (int k=0;k<10;k++){ e[k]=expf(u[k]-mx); s+=e[k]; }
        float run=0.f; cw[0]=-5.f;
        #pragma unroll
        for (int k=0;k<10;k++){ run += 0.001f + 0.99f*(e[k]/s); cw[k+1] = 10.f*run - 5.f; }
        cw[10] = 5.f;
        #pragma unroll
        for (int k=0;k<10;k++) wd[k] = cw[k+1]-cw[k];
    }
    float ch[11], hg[10];
    {
        float u[10]; float mx = -1e30f;
        #pragma unroll
        for (int k=0;k<10;k++){ u[k] = p[10+k]/SCALE; mx = fmaxf(mx,u[k]); }
        float s=0.f; float e[10];
        #pragma unroll
        for (int k=0;k<10;k++){ e[k]=expf(u[k]-mx); s+=e[k]; }
        float run=0.f; ch[0]=-5.f;
        #pragma unroll
        for (int k=0;k<10;k++){ run += 0.001f + 0.99f*(e[k]/s); ch[k+1] = 10.f*run - 5.f; }
        ch[10] = 5.f;
        #pragma unroll
        for (int k=0;k<10;k++) hg[k] = ch[k+1]-ch[k];
    }
    float dv[11];
    dv[0] = 1.0f; dv[10] = 1.0f;
    #pragma unroll
    for (int k=0;k<9;k++){
        float q = p[20+k];
        float sp = (q > 20.f) ? q : log1pf(expf(q));
        dv[k+1] = 0.001f + sp;
    }
    float xin = fminf(fmaxf(x1v, -5.f), 5.f);
    int cnt = 0;
    #pragma unroll
    for (int k=0;k<10;k++) cnt += (xin >= cw[k]) ? 1 : 0;
    int bin = cnt-1; if (bin < 0) bin = 0; if (bin > 9) bin = 9;

    float icw=cw[bin], iw=wd[bin], ich=ch[bin], ih=hg[bin];
    float dl=dv[bin], dr=dv[bin+1];
    float delta = ih/iw;
    float th  = (xin - icw)/iw;
    float t1m = th*(1.f-th);
    float num = ih*(delta*th*th + dl*t1m);
    float den = delta + (dl+dr-2.f*delta)*t1m;
    float yv  = ich + num/den;
    float onem = 1.f-th;
    float dnum = delta*delta*(dr*th*th + 2.f*delta*t1m + dl*onem*onem);
    float lad  = logf(dnum) - 2.f*logf(den);
    bool inside = (x1v >= -5.f) && (x1v <= 5.f);
    float xo   = inside ? yv  : x1v;
    float ladv = inside ? lad : 0.f;

    out[(size_t)b*2*TLEN + t]        = x0v * m;
    out[(size_t)b*2*TLEN + TLEN + t] = xo  * m;
    g_lad[pos] = ladv * m;
}

__global__ void logdet_kernel(float* __restrict__ out) {
    int b = blockIdx.x, tid = threadIdx.x;
    float s = 0.f;
    #pragma unroll
    for (int k=0;k<16;k++) s += g_lad[b*TLEN + k*256 + tid];
    __shared__ float smr[256];
    smr[tid] = s; __syncthreads();
    #pragma unroll
    for (int o=128;o;o>>=1){ if (tid<o) smr[tid]+=smr[tid+o]; __syncthreads(); }
    if (tid==0) out[b] = smr[0];
}

extern "C" void kernel_launch(void* const* d_in, const int* in_sizes, int n_in,
                              void* d_out, int out_size) {
    const float* x      = (const float*)d_in[0];
    const float* mask   = (const float*)d_in[1];
    const float* pre_w  = (const float*)d_in[2];
    const float* pre_b  = (const float*)d_in[3];
    const float* sep_w  = (const float*)d_in[4];
    const float* sep_b  = (const float*)d_in[5];
    const float* pw_w   = (const float*)d_in[6];
    const float* pw_b   = (const float*)d_in[7];
    const float* ln1_g  = (const float*)d_in[8];
    const float* ln1_b  = (const float*)d_in[9];
    const float* ln2_g  = (const float*)d_in[10];
    const float* ln2_b  = (const float*)d_in[11];
    const float* proj_w = (const float*)d_in[12];
    const float* proj_b = (const float*)d_in[13];
    float* out = (float*)d_out;

    float* hbuf[2];
    cudaGetSymbolAddress((void**)&hbuf[0], g_h0);
    cudaGetSymbolAddress((void**)&hbuf[1], g_h1);

    cudaFuncSetAttribute(fused_layer_mma,
                         cudaFuncAttributeMaxDynamicSharedMemorySize, SMEM_FL);
    cudaFuncSetAttribute(proj_mma,
                         cudaFuncAttributeMaxDynamicSharedMemorySize, PJ_SMEM);

    int d = 1;
    for (int i = 0; i < 3; i++) {
        int first = (i == 0);
        const float* hin = hbuf[(i+1) & 1];
        float* hout      = hbuf[i & 1];
        fused_layer_mma<<<BT/64, 256, SMEM_FL>>>(
            hin, hout,
            pw_w + (size_t)i*C*C, pw_b + (size_t)i*C,
            ln2_g + (size_t)i*C, ln2_b + (size_t)i*C,
            sep_w + (size_t)i*C*3, sep_b + (size_t)i*C,
            ln1_g + (size_t)i*C, ln1_b + (size_t)i*C,
            mask, x, pre_w, pre_b, d, first);
        d *= 3;
    }

    proj_mma<<<BT/32, 128, PJ_SMEM>>>(hbuf[0], proj_w, proj_b, mask);
    spline_kernel<<<BT/256, 256>>>(x, mask, out);
    logdet_kernel<<<64, 256>>>(out + (size_t)BATCH*2*TLEN);
}

// round 9
// speedup vs baseline: 2.1361x; 1.3598x over previous
#include <cuda_runtime.h>
#include <math.h>
#include <stdint.h>

#define BATCH 64
#define TLEN  4096
#define BT    (BATCH*TLEN)
#define C     192

__device__ float g_h0[(size_t)BT*C];
__device__ float g_h1[(size_t)BT*C];
__device__ float g_p[(size_t)BT*32];
__device__ float g_lad[BT];

__device__ __forceinline__ float geluf(float u) {
    return 0.5f*u*(1.f + erff(u*0.7071067811865475f));
}
__device__ __forceinline__ uint32_t smem_u32(const void* p) {
    uint32_t a;
    asm("{ .reg .u64 t; cvta.to.shared.u64 t, %1; cvt.u32.u64 %0, t; }" : "=r"(a) : "l"(p));
    return a;
}
__device__ __forceinline__ void cp16(uint32_t dst, const void* src) {
    asm volatile("cp.async.cg.shared.global [%0], [%1], 16;" :: "r"(dst), "l"(src));
}
#define CP_COMMIT() asm volatile("cp.async.commit_group;" ::: "memory")
#define CP_WAIT(n)  asm volatile("cp.async.wait_group %0;" :: "n"(n) : "memory")

// mma with k-remap: thread kq holds physical k = 2kq, 2kq+1 (consistent A/B)
__device__ __forceinline__ void mma_tf32(float* d, uint32_t a0, uint32_t a1,
                                         uint32_t a2, uint32_t a3,
                                         uint32_t b0, uint32_t b1) {
    asm volatile("mma.sync.aligned.m16n8k8.row.col.f32.tf32.tf32.f32 "
        "{%0,%1,%2,%3}, {%4,%5,%6,%7}, {%8,%9}, {%0,%1,%2,%3};"
        : "+f"(d[0]), "+f"(d[1]), "+f"(d[2]), "+f"(d[3])
        : "r"(a0), "r"(a1), "r"(a2), "r"(a3), "r"(b0), "r"(b1));
}

// layer smem (floats, natural fp32; strides 200/40 u32 -> banks ≡8 mod 32)
#define LY_YS_STR 200
#define LY_W_STR  40
#define LY_W_OFF  51200                 // bytes: 64*200*4
#define SMEM_FL   112640                // + 2*192*40*4

// ---------------------------------------------------------------------------
// Fused layer: 64 positions/block, 256 threads (8 warps: 4 M x 2 N)
// ---------------------------------------------------------------------------
__global__ __launch_bounds__(256, 2) void fused_layer_mma(
    const float* __restrict__ hin, float* __restrict__ hout,
    const float* __restrict__ W,  const float* __restrict__ bias,
    const float* __restrict__ g2, const float* __restrict__ b2,
    const float* __restrict__ sw, const float* __restrict__ sb,
    const float* __restrict__ g1, const float* __restrict__ b1,
    const float* __restrict__ mask, const float* __restrict__ x,
    const float* __restrict__ prew, const float* __restrict__ preb,
    int d, int first)
{
    extern __shared__ char smem[];
    float*    ysf = (float*)smem;                      // [64][200]
    uint32_t* ysu = (uint32_t*)smem;
    float*    Wc  = (float*)(smem + LY_W_OFF);         // [2][192][40]
    float*    ps1 = Wc;                                // reused post-GEMM
    float*    ps2 = Wc + 128;
    uint32_t  sW  = smem_u32(Wc);
    int tid = threadIdx.x, lane = tid & 31, w = tid >> 5;
    int m0 = blockIdx.x * 64;

    // issue W chunk kb via cp.async (raw fp32, natural layout)
    auto issueW = [&](int kb) {
        #pragma unroll
        for (int i = 0; i < 6; i++) {
            int idx = tid + i*256;                     // 0..1535
            int co = idx >> 3, q = idx & 7;
            uint32_t dst = sW + (uint32_t)((kb & 1)*192*LY_W_STR + co*LY_W_STR + q*4)*4u;
            cp16(dst, W + co*192 + kb*32 + q*4);
        }
        CP_COMMIT();
    };
    issueW(0); issueW(1);

    // ---- dw + LN1 + gelu -> ysf ; stash residual base into hout ----
    for (int r = 0; r < 8; r++) {
        int row = w*8 + r;
        int pos = m0 + row;
        int t = pos & 4095;
        float mC = mask[pos];
        bool hasL = (t >= d), hasR = (t + d < TLEN);
        float mL = hasL ? mask[pos-d] : 0.f;
        float mR = hasR ? mask[pos+d] : 0.f;
        const float* hrow = hin + (size_t)pos*C;
        float* horow = hout + (size_t)pos*C;
        float x0C=0.f, x0L=0.f, x0R=0.f;
        if (first) {
            const float* xr = x + (size_t)(pos >> 12)*2*TLEN;
            x0C = xr[t];
            if (hasL) x0L = xr[t-d];
            if (hasR) x0R = xr[t+d];
        }
        float v[6]; float s1 = 0.f, s2 = 0.f;
        #pragma unroll
        for (int k = 0; k < 6; k++) {
            int c = lane + 32*k;
            float hC, hL = 0.f, hR = 0.f;
            if (first) {
                float pw = prew[c], pb = preb[c];
                hC = fmaf(pw, x0C, pb);
                if (hasL) hL = fmaf(pw, x0L, pb);
                if (hasR) hR = fmaf(pw, x0R, pb);
            } else {
                hC = hrow[c];
                horow[c] = hC;                         // residual base stash
                if (hasL) hL = hrow[c - d*C];
                if (hasR) hR = hrow[c + d*C];
            }
            float y = sb[c];
            y = fmaf(sw[c*3+1], hC*mC, y);
            if (hasL) y = fmaf(sw[c*3+0], hL*mL, y);
            if (hasR) y = fmaf(sw[c*3+2], hR*mR, y);
            v[k] = y; s1 += y; s2 += y*y;
        }
        #pragma unroll
        for (int o=16;o;o>>=1) {                       // fused dual reduction
            s1 += __shfl_xor_sync(0xffffffffu, s1, o);
            s2 += __shfl_xor_sync(0xffffffffu, s2, o);
        }
        float mean = s1*(1.f/192.f);
        float var  = s2*(1.f/192.f) - mean*mean;
        float inv  = rsqrtf(var + 1e-5f);
        #pragma unroll
        for (int k=0;k<6;k++){
            int c = lane + 32*k;
            float u = fmaf(g1[c], (v[k]-mean)*inv, b1[c]);
            ysf[row*LY_YS_STR + c] = geluf(u);
        }
    }

    // ---- GEMM: warp (mw, nw) -> rows mw*16..+15, cols nw*96..+95 ----
    int mw = w & 3, nw = w >> 2;
    int gr = lane >> 2, kq = lane & 3;
    float acc[12][4];
    #pragma unroll
    for (int nf=0;nf<12;nf++)
        #pragma unroll
        for (int i=0;i<4;i++) acc[nf][i] = 0.f;

    #pragma unroll 1
    for (int kb = 0; kb < 6; kb++) {
        if (kb < 5) { CP_WAIT(1); } else { CP_WAIT(0); }
        __syncthreads();
        const float* wb = Wc + (kb & 1)*192*LY_W_STR;
        #pragma unroll
        for (int k4 = 0; k4 < 4; k4++) {
            int ko = kb*32 + k4*8 + kq*2;
            uint2 aP0 = *reinterpret_cast<const uint2*>(&ysu[(mw*16 + gr    )*LY_YS_STR + ko]);
            uint2 aP1 = *reinterpret_cast<const uint2*>(&ysu[(mw*16 + gr + 8)*LY_YS_STR + ko]);
            #pragma unroll
            for (int nf = 0; nf < 12; nf++) {
                int col = nw*96 + nf*8 + gr;
                uint2 bP = *reinterpret_cast<const uint2*>(&wb[col*LY_W_STR + k4*8 + kq*2]);
                mma_tf32(acc[nf], aP0.x, aP1.x, aP0.y, aP1.y, bP.x, bP.y);
            }
        }
        __syncthreads();
        if (kb + 2 < 6) issueW(kb + 2);
    }

    // ---- epilogue: bias, LN2, gelu -> ysf ----
    {
        float s1r0=0.f, s2r0=0.f, s1r1=0.f, s2r1=0.f;
        #pragma unroll
        for (int nf = 0; nf < 12; nf++) {
            int c0 = nw*96 + nf*8 + kq*2;
            float bv0 = bias[c0], bv1 = bias[c0+1];
            acc[nf][0] += bv0; acc[nf][1] += bv1;
            acc[nf][2] += bv0; acc[nf][3] += bv1;
            s1r0 += acc[nf][0] + acc[nf][1];
            s2r0 += acc[nf][0]*acc[nf][0] + acc[nf][1]*acc[nf][1];
            s1r1 += acc[nf][2] + acc[nf][3];
            s2r1 += acc[nf][2]*acc[nf][2] + acc[nf][3]*acc[nf][3];
        }
        #pragma unroll
        for (int o = 1; o <= 2; o <<= 1) {
            s1r0 += __shfl_xor_sync(0xffffffffu, s1r0, o);
            s2r0 += __shfl_xor_sync(0xffffffffu, s2r0, o);
            s1r1 += __shfl_xor_sync(0xffffffffu, s1r1, o);
            s2r1 += __shfl_xor_sync(0xffffffffu, s2r1, o);
        }
        int row0 = mw*16 + gr, row1 = row0 + 8;
        if (kq == 0) {
            ps1[nw*64 + row0] = s1r0; ps2[nw*64 + row0] = s2r0;
            ps1[nw*64 + row1] = s1r1; ps2[nw*64 + row1] = s2r1;
        }
        __syncthreads();
        float S10 = ps1[row0] + ps1[64 + row0];
        float S20 = ps2[row0] + ps2[64 + row0];
        float S11 = ps1[row1] + ps1[64 + row1];
        float S21 = ps2[row1] + ps2[64 + row1];
        float mean0 = S10*(1.f/192.f);
        float inv0  = rsqrtf(S20*(1.f/192.f) - mean0*mean0 + 1e-5f);
        float mean1 = S11*(1.f/192.f);
        float inv1  = rsqrtf(S21*(1.f/192.f) - mean1*mean1 + 1e-5f);
        __syncthreads();
        #pragma unroll
        for (int nf = 0; nf < 12; nf++) {
            int c0 = nw*96 + nf*8 + kq*2;
            float ga = g2[c0], gb = g2[c0+1], ba = b2[c0], bb = b2[c0+1];
            ysf[row0*LY_YS_STR + c0    ] = geluf(fmaf(ga, (acc[nf][0]-mean0)*inv0, ba));
            ysf[row0*LY_YS_STR + c0 + 1] = geluf(fmaf(gb, (acc[nf][1]-mean0)*inv0, bb));
            ysf[row1*LY_YS_STR + c0    ] = geluf(fmaf(ga, (acc[nf][2]-mean1)*inv1, ba));
            ysf[row1*LY_YS_STR + c0 + 1] = geluf(fmaf(gb, (acc[nf][3]-mean1)*inv1, bb));
        }
    }
    __syncthreads();

    // ---- residual + store (base from hout stash: L1/L2 hit) ----
    for (int r = 0; r < 8; r++) {
        int row = w*8 + r;
        int pos = m0 + row;
        size_t rowo = (size_t)pos*C;
        float x0v = 0.f;
        if (first) x0v = x[(size_t)(pos >> 12)*2*TLEN + (pos & 4095)];
        #pragma unroll
        for (int k = 0; k < 6; k++) {
            int c = lane + 32*k;
            float base = first ? fmaf(prew[c], x0v, preb[c]) : hout[rowo + c];
            hout[rowo + c] = base + ysf[row*LY_YS_STR + c];
        }
    }
}

// ---------------------------------------------------------------------------
// proj via mma: 64 positions/block, 256 threads (4 M-warps x 2 K-split)
// raw fp32 smem via cp.async, k-remapped fragments, stride 200
// ---------------------------------------------------------------------------
#define PJ_HS   0                        // fp32 [64][200]
#define PJ_WS   51200                    // fp32 [32][200] (rows 29..31 unused)
#define PJ_PS   76800                    // fp32 [64][33]
#define PJ_SMEM 85248

__global__ __launch_bounds__(256) void proj_mma(
    const float* __restrict__ h,
    const float* __restrict__ Wp, const float* __restrict__ bp,
    const float* __restrict__ mask)
{
    extern __shared__ char smem[];
    uint32_t* hs  = (uint32_t*)(smem + PJ_HS);
    uint32_t* wps = (uint32_t*)(smem + PJ_WS);
    float*    ps  = (float*)(smem + PJ_PS);
    uint32_t  sb  = smem_u32(smem);
    int tid = threadIdx.x, lane = tid & 31, w = tid >> 5;
    int m0 = blockIdx.x * 64;

    // h rows: 64 x 48 float4 = 3072 chunks
    #pragma unroll
    for (int i = 0; i < 12; i++) {
        int idx = tid + i*256;
        int row = idx / 48, q = idx % 48;
        cp16(sb + (uint32_t)(PJ_HS) + (uint32_t)(row*200 + q*4)*4u,
             h + (size_t)(m0+row)*C + q*4);
    }
    // Wp: 29 x 48 float4 = 1392 chunks
    #pragma unroll
    for (int i = 0; i < 6; i++) {
        int idx = tid + i*256;
        if (idx < 29*48) {
            int j = idx / 48, q = idx % 48;
            cp16(sb + (uint32_t)(PJ_WS) + (uint32_t)(j*200 + q*4)*4u,
                 Wp + j*192 + q*4);
        }
    }
    CP_COMMIT();
    CP_WAIT(0);
    __syncthreads();

    int mw = w & 3, kw = w >> 2;       // 4 M-tiles x 2 K-halves
    int gr = lane >> 2, kq = lane & 3;
    float acc[4][4];
    #pragma unroll
    for (int nf=0;nf<4;nf++)
        #pragma unroll
        for (int i=0;i<4;i++) acc[nf][i] = 0.f;

    #pragma unroll
    for (int ks = 0; ks < 12; ks++) {
        int ko = kw*96 + ks*8 + kq*2;
        uint2 aP0 = *reinterpret_cast<const uint2*>(&hs[(mw*16 + gr    )*200 + ko]);
        uint2 aP1 = *reinterpret_cast<const uint2*>(&hs[(mw*16 + gr + 8)*200 + ko]);
        #pragma unroll
        for (int nf = 0; nf < 4; nf++) {
            uint2 bP = *reinterpret_cast<const uint2*>(&wps[(nf*8 + gr)*200 + ko]);
            mma_tf32(acc[nf], aP0.x, aP1.x, aP0.y, aP1.y, bP.x, bP.y);
        }
    }

    if (kw == 0) {
        #pragma unroll
        for (int nf = 0; nf < 4; nf++) {
            int j = nf*8 + kq*2;
            ps[(mw*16 + gr    )*33 + j    ] = acc[nf][0];
            ps[(mw*16 + gr    )*33 + j + 1] = acc[nf][1];
            ps[(mw*16 + gr + 8)*33 + j    ] = acc[nf][2];
            ps[(mw*16 + gr + 8)*33 + j + 1] = acc[nf][3];
        }
    }
    __syncthreads();
    if (kw == 1) {
        int row0 = mw*16 + gr, row1 = row0 + 8;
        float mA = mask[m0 + row0];
        float mB = mask[m0 + row1];
        float* gpA = g_p + (size_t)(m0 + row0)*32;
        float* gpB = g_p + (size_t)(m0 + row1)*32;
        #pragma unroll
        for (int nf = 0; nf < 4; nf++) {
            int j = nf*8 + kq*2;
            #pragma unroll
            for (int e = 0; e < 2; e++) {
                int jj = j + e;
                if (jj < 29) {
                    float bv = bp[jj];
                    gpA[jj] = fmaf(mA, acc[nf][e  ] + ps[row0*33 + jj], bv) * mA;
                    gpB[jj] = fmaf(mB, acc[nf][e+2] + ps[row1*33 + jj], bv) * mB;
                }
            }
        }
    }
}

// ---------------------------------------------------------------------------
// rational-quadratic spline
// ---------------------------------------------------------------------------
__global__ __launch_bounds__(256) void spline_kernel(
    const float* __restrict__ x, const float* __restrict__ mask,
    float* __restrict__ out)
{
    int pos = blockIdx.x*256 + threadIdx.x;
    int b = pos >> 12, t = pos & 4095;
    float m = mask[pos];
    const float* p = g_p + (size_t)pos*32;
    const float SCALE = 13.856406460551018f;

    float x0v = x[(size_t)b*2*TLEN + t];
    float x1v = x[(size_t)b*2*TLEN + TLEN + t];

    float cw[11], wd[10];
    {
        float u[10]; float mx = -1e30f;
        #pragma unroll
        for (int k=0;k<10;k++){ u[k] = p[k]/SCALE; mx = fmaxf(mx,u[k]); }
        float s=0.f; float e[10];
        #pragma unroll
        for (int k=0;k<10;k++){ e[k]=expf(u[k]-mx); s+=e[k]; }
        float run=0.f; cw[0]=-5.f;
        #pragma unroll
        for (int k=0;k<10;k++){ run += 0.001f + 0.99f*(e[k]/s); cw[k+1] = 10.f*run - 5.f; }
        cw[10] = 5.f;
        #pragma unroll
        for (int k=0;k<10;k++) wd[k] = cw[k+1]-cw[k];
    }
    float ch[11], hg[10];
    {
        float u[10]; float mx = -1e30f;
        #pragma unroll
        for (int k=0;k<10;k++){ u[k] = p[10+k]/SCALE; mx = fmaxf(mx,u[k]); }
        float s=0.f; float e[10];
        #pragma unroll
        for (int k=0;k<10;k++){ e[k]=expf(u[k]-mx); s+=e[k]; }
        float run=0.f; ch[0]=-5.f;
        #pragma unroll
        for (int k=0;k<10;k++){ run += 0.001f + 0.99f*(e[k]/s); ch[k+1] = 10.f*run - 5.f; }
        ch[10] = 5.f;
        #pragma unroll
        for (int k=0;k<10;k++) hg[k] = ch[k+1]-ch[k];
    }
    float dv[11];
    dv[0] = 1.0f; dv[10] = 1.0f;
    #pragma unroll
    for (int k=0;k<9;k++){
        float q = p[20+k];
        float sp = (q > 20.f) ? q : log1pf(expf(q));
        dv[k+1] = 0.001f + sp;
    }
    float xin = fminf(fmaxf(x1v, -5.f), 5.f);
    int cnt = 0;
    #pragma unroll
    for (int k=0;k<10;k++) cnt += (xin >= cw[k]) ? 1 : 0;
    int bin = cnt-1; if (bin < 0) bin = 0; if (bin > 9) bin = 9;

    float icw=cw[bin], iw=wd[bin], ich=ch[bin], ih=hg[bin];
    float dl=dv[bin], dr=dv[bin+1];
    float delta = ih/iw;
    float th  = (xin - icw)/iw;
    float t1m = th*(1.f-th);
    float num = ih*(delta*th*th + dl*t1m);
    float den = delta + (dl+dr-2.f*delta)*t1m;
    float yv  = ich + num/den;
    float onem = 1.f-th;
    float dnum = delta*delta*(dr*th*th + 2.f*delta*t1m + dl*onem*onem);
    float lad  = logf(dnum) - 2.f*logf(den);
    bool inside = (x1v >= -5.f) && (x1v <= 5.f);
    float xo   = inside ? yv  : x1v;
    float ladv = inside ? lad : 0.f;

    out[(size_t)b*2*TLEN + t]        = x0v * m;
    out[(size_t)b*2*TLEN + TLEN + t] = xo  * m;
    g_lad[pos] = ladv * m;
}

__global__ void logdet_kernel(float* __restrict__ out) {
    int b = blockIdx.x, tid = threadIdx.x;
    float s = 0.f;
    #pragma unroll
    for (int k=0;k<16;k++) s += g_lad[b*TLEN + k*256 + tid];
    __shared__ float smr[256];
    smr[tid] = s; __syncthreads();
    #pragma unroll
    for (int o=128;o;o>>=1){ if (tid<o) smr[tid]+=smr[tid+o]; __syncthreads(); }
    if (tid==0) out[b] = smr[0];
}

extern "C" void kernel_launch(void* const* d_in, const int* in_sizes, int n_in,
                              void* d_out, int out_size) {
    const float* x      = (const float*)d_in[0];
    const float* mask   = (const float*)d_in[1];
    const float* pre_w  = (const float*)d_in[2];
    const float* pre_b  = (const float*)d_in[3];
    const float* sep_w  = (const float*)d_in[4];
    const float* sep_b  = (const float*)d_in[5];
    const float* pw_w   = (const float*)d_in[6];
    const float* pw_b   = (const float*)d_in[7];
    const float* ln1_g  = (const float*)d_in[8];
    const float* ln1_b  = (const float*)d_in[9];
    const float* ln2_g  = (const float*)d_in[10];
    const float* ln2_b  = (const float*)d_in[11];
    const float* proj_w = (const float*)d_in[12];
    const float* proj_b = (const float*)d_in[13];
    float* out = (float*)d_out;

    float* hbuf[2];
    cudaGetSymbolAddress((void**)&hbuf[0], g_h0);
    cudaGetSymbolAddress((void**)&hbuf[1], g_h1);

    cudaFuncSetAttribute(fused_layer_mma,
                         cudaFuncAttributeMaxDynamicSharedMemorySize, SMEM_FL);
    cudaFuncSetAttribute(proj_mma,
                         cudaFuncAttributeMaxDynamicSharedMemorySize, PJ_SMEM);

    int d = 1;
    for (int i = 0; i < 3; i++) {
        int first = (i == 0);
        const float* hin = hbuf[(i+1) & 1];
        float* hout      = hbuf[i & 1];
        fused_layer_mma<<<BT/64, 256, SMEM_FL>>>(
            hin, hout,
            pw_w + (size_t)i*C*C, pw_b + (size_t)i*C,
            ln2_g + (size_t)i*C, ln2_b + (size_t)i*C,
            sep_w + (size_t)i*C*3, sep_b + (size_t)i*C,
            ln1_g + (size_t)i*C, ln1_b + (size_t)i*C,
            mask, x, pre_w, pre_b, d, first);
        d *= 3;
    }

    proj_mma<<<BT/64, 256, PJ_SMEM>>>(hbuf[0], proj_w, proj_b, mask);
    spline_kernel<<<BT/256, 256>>>(x, mask, out);
    logdet_kernel<<<64, 256>>>(out + (size_t)BATCH*2*TLEN);
}

// round 10
// speedup vs baseline: 2.3402x; 1.0956x over previous
#include <cuda_runtime.h>
#include <math.h>
#include <stdint.h>

#define BATCH 64
#define TLEN  4096
#define BT    (BATCH*TLEN)
#define C     192

__device__ float g_h0[(size_t)BT*C];
__device__ float g_h1[(size_t)BT*C];
__device__ float g_p[(size_t)BT*32];
__device__ float g_lad[BT];

__device__ __forceinline__ float geluf(float u) {
    return 0.5f*u*(1.f + erff(u*0.7071067811865475f));
}
__device__ __forceinline__ uint32_t smem_u32(const void* p) {
    uint32_t a;
    asm("{ .reg .u64 t; cvta.to.shared.u64 t, %1; cvt.u32.u64 %0, t; }" : "=r"(a) : "l"(p));
    return a;
}
__device__ __forceinline__ void cp16(uint32_t dst, const void* src) {
    asm volatile("cp.async.cg.shared.global [%0], [%1], 16;" :: "r"(dst), "l"(src));
}
#define CP_COMMIT() asm volatile("cp.async.commit_group;" ::: "memory")
#define CP_WAIT(n)  asm volatile("cp.async.wait_group %0;" :: "n"(n) : "memory")

// mma with k-remap: thread kq holds physical k = 2kq, 2kq+1 (consistent A/B)
__device__ __forceinline__ void mma_tf32(float* d, uint32_t a0, uint32_t a1,
                                         uint32_t a2, uint32_t a3,
                                         uint32_t b0, uint32_t b1) {
    asm volatile("mma.sync.aligned.m16n8k8.row.col.f32.tf32.tf32.f32 "
        "{%0,%1,%2,%3}, {%4,%5,%6,%7}, {%8,%9}, {%0,%1,%2,%3};"
        : "+f"(d[0]), "+f"(d[1]), "+f"(d[2]), "+f"(d[3])
        : "r"(a0), "r"(a1), "r"(a2), "r"(a3), "r"(b0), "r"(b1));
}

#define LY_YS_STR 200
#define LY_W_STR  40
#define LY_W_OFF  51200                 // bytes: 64*200*4
#define SMEM_FL   112640                // + 2*192*40*4

// ---------------------------------------------------------------------------
// Fused layer: 64 positions/block, 256 threads (8 warps: 4 M x 2 N)
// last=1: also computes proj (h @ Wp^T) in-kernel, skips hout final store
// ---------------------------------------------------------------------------
__global__ __launch_bounds__(256, 2) void fused_layer_mma(
    const float* __restrict__ hin, float* __restrict__ hout,
    const float* __restrict__ W,  const float* __restrict__ bias,
    const float* __restrict__ g2, const float* __restrict__ b2,
    const float* __restrict__ sw, const float* __restrict__ sb,
    const float* __restrict__ g1, const float* __restrict__ b1,
    const float* __restrict__ mask, const float* __restrict__ x,
    const float* __restrict__ prew, const float* __restrict__ preb,
    const float* __restrict__ Wp,  const float* __restrict__ bpj,
    int d, int first, int last)
{
    extern __shared__ char smem[];
    float*    ysf = (float*)smem;                      // [64][200]
    uint32_t* ysu = (uint32_t*)smem;
    float*    Wc  = (float*)(smem + LY_W_OFF);         // [2][192][40]
    float*    ps1 = Wc + 192*LY_W_STR;                 // buf1 region (post-GEMM)
    float*    ps2 = ps1 + 128;
    float*    psP = ps1 + 256;                         // [64][33] proj partials
    uint32_t  sW  = smem_u32(Wc);
    int tid = threadIdx.x, lane = tid & 31, w = tid >> 5;
    int m0 = blockIdx.x * 64;

    auto issueW = [&](int kb) {
        #pragma unroll
        for (int i = 0; i < 6; i++) {
            int idx = tid + i*256;
            int co = idx >> 3, q = idx & 7;
            uint32_t dst = sW + (uint32_t)((kb & 1)*192*LY_W_STR + co*LY_W_STR + q*4)*4u;
            cp16(dst, W + co*192 + kb*32 + q*4);
        }
        CP_COMMIT();
    };
    issueW(0); issueW(1);

    // ---- dw + LN1 + gelu -> ysf (2-row pipeline); stash residual base ----
    for (int rp = 0; rp < 4; rp++) {
        int rowB = w*8 + rp*2;
        float v[2][6], s1[2], s2[2];
        float mC[2], mL[2], mR[2];
        bool hasL[2], hasR[2];
        const float* hrow[2];
        float* horow[2];
        float x0C[2], x0L[2], x0R[2];
        #pragma unroll
        for (int u = 0; u < 2; u++) {
            int pos = m0 + rowB + u;
            int t = pos & 4095;
            mC[u] = mask[pos];
            hasL[u] = (t >= d); hasR[u] = (t + d < TLEN);
            mL[u] = hasL[u] ? mask[pos-d] : 0.f;
            mR[u] = hasR[u] ? mask[pos+d] : 0.f;
            hrow[u]  = hin  + (size_t)pos*C;
            horow[u] = hout + (size_t)pos*C;
            x0C[u]=0.f; x0L[u]=0.f; x0R[u]=0.f;
            if (first) {
                const float* xr = x + (size_t)(pos >> 12)*2*TLEN;
                x0C[u] = xr[t];
                if (hasL[u]) x0L[u] = xr[t-d];
                if (hasR[u]) x0R[u] = xr[t+d];
            }
            s1[u]=0.f; s2[u]=0.f;
        }
        #pragma unroll
        for (int k = 0; k < 6; k++) {
            int c = lane + 32*k;
            #pragma unroll
            for (int u = 0; u < 2; u++) {
                float hC, hL = 0.f, hR = 0.f;
                if (first) {
                    float pw = prew[c], pb = preb[c];
                    hC = fmaf(pw, x0C[u], pb);
                    if (hasL[u]) hL = fmaf(pw, x0L[u], pb);
                    if (hasR[u]) hR = fmaf(pw, x0R[u], pb);
                } else {
                    hC = hrow[u][c];
                    horow[u][c] = hC;
                    if (hasL[u]) hL = hrow[u][c - d*C];
                    if (hasR[u]) hR = hrow[u][c + d*C];
                }
                float y = sb[c];
                y = fmaf(sw[c*3+1], hC*mC[u], y);
                if (hasL[u]) y = fmaf(sw[c*3+0], hL*mL[u], y);
                if (hasR[u]) y = fmaf(sw[c*3+2], hR*mR[u], y);
                v[u][k] = y; s1[u] += y; s2[u] += y*y;
            }
        }
        #pragma unroll
        for (int o=16;o;o>>=1) {
            s1[0] += __shfl_xor_sync(0xffffffffu, s1[0], o);
            s2[0] += __shfl_xor_sync(0xffffffffu, s2[0], o);
            s1[1] += __shfl_xor_sync(0xffffffffu, s1[1], o);
            s2[1] += __shfl_xor_sync(0xffffffffu, s2[1], o);
        }
        #pragma unroll
        for (int u = 0; u < 2; u++) {
            float mean = s1[u]*(1.f/192.f);
            float var  = s2[u]*(1.f/192.f) - mean*mean;
            float inv  = rsqrtf(var + 1e-5f);
            #pragma unroll
            for (int k=0;k<6;k++){
                int c = lane + 32*k;
                float uu = fmaf(g1[c], (v[u][k]-mean)*inv, b1[c]);
                ysf[(rowB+u)*LY_YS_STR + c] = geluf(uu);
            }
        }
    }

    // ---- GEMM: warp (mw, nw) -> rows mw*16..+15, cols nw*96..+95 ----
    int mw = w & 3, nw = w >> 2;
    int gr = lane >> 2, kq = lane & 3;
    float acc[12][4];
    #pragma unroll
    for (int nf=0;nf<12;nf++)
        #pragma unroll
        for (int i=0;i<4;i++) acc[nf][i] = 0.f;

    #pragma unroll 1
    for (int kb = 0; kb < 6; kb++) {
        if (kb < 5) { CP_WAIT(1); } else { CP_WAIT(0); }
        __syncthreads();
        const float* wb = Wc + (kb & 1)*192*LY_W_STR;
        #pragma unroll
        for (int k4 = 0; k4 < 4; k4++) {
            int ko = kb*32 + k4*8 + kq*2;
            uint2 aP0 = *reinterpret_cast<const uint2*>(&ysu[(mw*16 + gr    )*LY_YS_STR + ko]);
            uint2 aP1 = *reinterpret_cast<const uint2*>(&ysu[(mw*16 + gr + 8)*LY_YS_STR + ko]);
            #pragma unroll
            for (int nf = 0; nf < 12; nf++) {
                int col = nw*96 + nf*8 + gr;
                uint2 bP = *reinterpret_cast<const uint2*>(&wb[col*LY_W_STR + k4*8 + kq*2]);
                mma_tf32(acc[nf], aP0.x, aP1.x, aP0.y, aP1.y, bP.x, bP.y);
            }
        }
        __syncthreads();
        if (kb + 2 < 6) issueW(kb + 2);
        if (last && kb == 4) {
            // Wp -> buf0 region (chunk 4 consumed; kb=5 reads buf1 only)
            #pragma unroll
            for (int i = 0; i < 6; i++) {
                int idx = tid + i*256;
                if (idx < 29*48) {
                    int j = idx / 48, q = idx % 48;
                    cp16(sW + (uint32_t)(j*LY_YS_STR + q*4)*4u, Wp + j*192 + q*4);
                }
            }
            CP_COMMIT();
        }
    }

    // ---- epilogue: bias, LN2, gelu -> ysf ----
    {
        float s1r0=0.f, s2r0=0.f, s1r1=0.f, s2r1=0.f;
        #pragma unroll
        for (int nf = 0; nf < 12; nf++) {
            int c0 = nw*96 + nf*8 + kq*2;
            float bv0 = bias[c0], bv1 = bias[c0+1];
            acc[nf][0] += bv0; acc[nf][1] += bv1;
            acc[nf][2] += bv0; acc[nf][3] += bv1;
            s1r0 += acc[nf][0] + acc[nf][1];
            s2r0 += acc[nf][0]*acc[nf][0] + acc[nf][1]*acc[nf][1];
            s1r1 += acc[nf][2] + acc[nf][3];
            s2r1 += acc[nf][2]*acc[nf][2] + acc[nf][3]*acc[nf][3];
        }
        #pragma unroll
        for (int o = 1; o <= 2; o <<= 1) {
            s1r0 += __shfl_xor_sync(0xffffffffu, s1r0, o);
            s2r0 += __shfl_xor_sync(0xffffffffu, s2r0, o);
            s1r1 += __shfl_xor_sync(0xffffffffu, s1r1, o);
            s2r1 += __shfl_xor_sync(0xffffffffu, s2r1, o);
        }
        int row0 = mw*16 + gr, row1 = row0 + 8;
        if (kq == 0) {
            ps1[nw*64 + row0] = s1r0; ps2[nw*64 + row0] = s2r0;
            ps1[nw*64 + row1] = s1r1; ps2[nw*64 + row1] = s2r1;
        }
        __syncthreads();
        float S10 = ps1[row0] + ps1[64 + row0];
        float S20 = ps2[row0] + ps2[64 + row0];
        float S11 = ps1[row1] + ps1[64 + row1];
        float S21 = ps2[row1] + ps2[64 + row1];
        float mean0 = S10*(1.f/192.f);
        float inv0  = rsqrtf(S20*(1.f/192.f) - mean0*mean0 + 1e-5f);
        float mean1 = S11*(1.f/192.f);
        float inv1  = rsqrtf(S21*(1.f/192.f) - mean1*mean1 + 1e-5f);
        __syncthreads();
        #pragma unroll
        for (int nf = 0; nf < 12; nf++) {
            int c0 = nw*96 + nf*8 + kq*2;
            float ga = g2[c0], gb = g2[c0+1], ba = b2[c0], bb = b2[c0+1];
            ysf[row0*LY_YS_STR + c0    ] = geluf(fmaf(ga, (acc[nf][0]-mean0)*inv0, ba));
            ysf[row0*LY_YS_STR + c0 + 1] = geluf(fmaf(gb, (acc[nf][1]-mean0)*inv0, bb));
            ysf[row1*LY_YS_STR + c0    ] = geluf(fmaf(ga, (acc[nf][2]-mean1)*inv1, ba));
            ysf[row1*LY_YS_STR + c0 + 1] = geluf(fmaf(gb, (acc[nf][3]-mean1)*inv1, bb));
        }
    }
    __syncthreads();

    // ---- residual; last: h -> ysf (for proj), else h -> hout ----
    for (int r = 0; r < 8; r++) {
        int row = w*8 + r;
        int pos = m0 + row;
        size_t rowo = (size_t)pos*C;
        float x0v = 0.f;
        if (first) x0v = x[(size_t)(pos >> 12)*2*TLEN + (pos & 4095)];
        #pragma unroll
        for (int k = 0; k < 6; k++) {
            int c = lane + 32*k;
            float base = first ? fmaf(prew[c], x0v, preb[c]) : hout[rowo + c];
            float hv = base + ysf[row*LY_YS_STR + c];
            if (last) ysf[row*LY_YS_STR + c] = hv;
            else      hout[rowo + c] = hv;
        }
    }

    // ---- fused proj (last layer): p = h @ Wp^T, M=64, N=32(29), K=192 ----
    if (last) {
        __syncthreads();
        const uint32_t* WpS = (const uint32_t*)Wc;   // [29][200]
        int mw2 = w & 3, kw2 = w >> 2;
        float pacc[4][4];
        #pragma unroll
        for (int nf=0;nf<4;nf++)
            #pragma unroll
            for (int i=0;i<4;i++) pacc[nf][i] = 0.f;
        #pragma unroll
        for (int ks = 0; ks < 12; ks++) {
            int ko = kw2*96 + ks*8 + kq*2;
            uint2 aP0 = *reinterpret_cast<const uint2*>(&ysu[(mw2*16 + gr    )*LY_YS_STR + ko]);
            uint2 aP1 = *reinterpret_cast<const uint2*>(&ysu[(mw2*16 + gr + 8)*LY_YS_STR + ko]);
            #pragma unroll
            for (int nf = 0; nf < 4; nf++) {
                uint2 bP = *reinterpret_cast<const uint2*>(&WpS[(nf*8 + gr)*LY_YS_STR + ko]);
                mma_tf32(pacc[nf], aP0.x, aP1.x, aP0.y, aP1.y, bP.x, bP.y);
            }
        }
        if (kw2 == 0) {
            #pragma unroll
            for (int nf = 0; nf < 4; nf++) {
                int j = nf*8 + kq*2;
                psP[(mw2*16 + gr    )*33 + j    ] = pacc[nf][0];
                psP[(mw2*16 + gr    )*33 + j + 1] = pacc[nf][1];
                psP[(mw2*16 + gr + 8)*33 + j    ] = pacc[nf][2];
                psP[(mw2*16 + gr + 8)*33 + j + 1] = pacc[nf][3];
            }
        }
        __syncthreads();
        if (kw2 == 1) {
            int row0 = mw2*16 + gr, row1 = row0 + 8;
            float mA = mask[m0 + row0];
            float mB = mask[m0 + row1];
            float* gpA = g_p + (size_t)(m0 + row0)*32;
            float* gpB = g_p + (size_t)(m0 + row1)*32;
            #pragma unroll
            for (int nf = 0; nf < 4; nf++) {
                int j = nf*8 + kq*2;
                #pragma unroll
                for (int e = 0; e < 2; e++) {
                    int jj = j + e;
                    if (jj < 29) {
                        float bv = bpj[jj];
                        gpA[jj] = fmaf(mA, pacc[nf][e  ] + psP[row0*33 + jj], bv) * mA;
                        gpB[jj] = fmaf(mB, pacc[nf][e+2] + psP[row1*33 + jj], bv) * mB;
                    }
                }
            }
        }
    }
}

// ---------------------------------------------------------------------------
// rational-quadratic spline (fast math: __expf/__logf/__fdividef)
// ---------------------------------------------------------------------------
__global__ __launch_bounds__(256) void spline_kernel(
    const float* __restrict__ x, const float* __restrict__ mask,
    float* __restrict__ out)
{
    int pos = blockIdx.x*256 + threadIdx.x;
    int b = pos >> 12, t = pos & 4095;
    float m = mask[pos];
    const float* p = g_p + (size_t)pos*32;
    const float ISCALE = 0.07216878364870323f;   // 1/sqrt(192)

    float x0v = x[(size_t)b*2*TLEN + t];
    float x1v = x[(size_t)b*2*TLEN + TLEN + t];

    float cw[11], wd[10];
    {
        float u[10]; float mx = -1e30f;
        #pragma unroll
        for (int k=0;k<10;k++){ u[k] = p[k]*ISCALE; mx = fmaxf(mx,u[k]); }
        float s=0.f; float e[10];
        #pragma unroll
        for (int k=0;k<10;k++){ e[k]=__expf(u[k]-mx); s+=e[k]; }
        float rs = __fdividef(1.f, s);
        float run=0.f; cw[0]=-5.f;
        #pragma unroll
        for (int k=0;k<10;k++){ run += 0.001f + 0.99f*e[k]*rs; cw[k+1] = 10.f*run - 5.f; }
        cw[10] = 5.f;
        #pragma unroll
        for (int k=0;k<10;k++) wd[k] = cw[k+1]-cw[k];
    }
    float ch[11], hg[10];
    {
        float u[10]; float mx = -1e30f;
        #pragma unroll
        for (int k=0;k<10;k++){ u[k] = p[10+k]*ISCALE; mx = fmaxf(mx,u[k]); }
        float s=0.f; float e[10];
        #pragma unroll
        for (int k=0;k<10;k++){ e[k]=__expf(u[k]-mx); s+=e[k]; }
        float rs = __fdividef(1.f, s);
        float run=0.f; ch[0]=-5.f;
        #pragma unroll
        for (int k=0;k<10;k++){ run += 0.001f + 0.99f*e[k]*rs; ch[k+1] = 10.f*run - 5.f; }
        ch[10] = 5.f;
        #pragma unroll
        for (int k=0;k<10;k++) hg[k] = ch[k+1]-ch[k];
    }
    float dv[11];
    dv[0] = 1.0f; dv[10] = 1.0f;
    #pragma unroll
    for (int k=0;k<9;k++){
        float q = p[20+k];
        float sp = (q > 20.f) ? q : __logf(1.f + __expf(q));
        dv[k+1] = 0.001f + sp;
    }
    float xin = fminf(fmaxf(x1v, -5.f), 5.f);
    int cnt = 0;
    #pragma unroll
    for (int k=0;k<10;k++) cnt += (xin >= cw[k]) ? 1 : 0;
    int bin = cnt-1; if (bin < 0) bin = 0; if (bin > 9) bin = 9;

    float icw=cw[bin], iw=wd[bin], ich=ch[bin], ih=hg[bin];
    float dl=dv[bin], dr=dv[bin+1];
    float riw = __fdividef(1.f, iw);
    float delta = ih*riw;
    float th  = (xin - icw)*riw;
    float t1m = th*(1.f-th);
    float num = ih*(delta*th*th + dl*t1m);
    float den = delta + (dl+dr-2.f*delta)*t1m;
    float yv  = ich + __fdividef(num, den);
    float onem = 1.f-th;
    float dnum = delta*delta*(dr*th*th + 2.f*delta*t1m + dl*onem*onem);
    float lad  = __logf(dnum) - 2.f*__logf(den);
    bool inside = (x1v >= -5.f) && (x1v <= 5.f);
    float xo   = inside ? yv  : x1v;
    float ladv = inside ? lad : 0.f;

    out[(size_t)b*2*TLEN + t]        = x0v * m;
    out[(size_t)b*2*TLEN + TLEN + t] = xo  * m;
    g_lad[pos] = ladv * m;
}

__global__ void logdet_kernel(float* __restrict__ out) {
    int b = blockIdx.x, tid = threadIdx.x;
    float s = 0.f;
    #pragma unroll
    for (int k=0;k<16;k++) s += g_lad[b*TLEN + k*256 + tid];
    __shared__ float smr[256];
    smr[tid] = s; __syncthreads();
    #pragma unroll
    for (int o=128;o;o>>=1){ if (tid<o) smr[tid]+=smr[tid+o]; __syncthreads(); }
    if (tid==0) out[b] = smr[0];
}

extern "C" void kernel_launch(void* const* d_in, const int* in_sizes, int n_in,
                              void* d_out, int out_size) {
    const float* x      = (const float*)d_in[0];
    const float* mask   = (const float*)d_in[1];
    const float* pre_w  = (const float*)d_in[2];
    const float* pre_b  = (const float*)d_in[3];
    const float* sep_w  = (const float*)d_in[4];
    const float* sep_b  = (const float*)d_in[5];
    const float* pw_w   = (const float*)d_in[6];
    const float* pw_b   = (const float*)d_in[7];
    const float* ln1_g  = (const float*)d_in[8];
    const float* ln1_b  = (const float*)d_in[9];
    const float* ln2_g  = (const float*)d_in[10];
    const float* ln2_b  = (const float*)d_in[11];
    const float* proj_w = (const float*)d_in[12];
    const float* proj_b = (const float*)d_in[13];
    float* out = (float*)d_out;

    float* hbuf[2];
    cudaGetSymbolAddress((void**)&hbuf[0], g_h0);
    cudaGetSymbolAddress((void**)&hbuf[1], g_h1);

    cudaFuncSetAttribute(fused_layer_mma,
                         cudaFuncAttributeMaxDynamicSharedMemorySize, SMEM_FL);

    int d = 1;
    for (int i = 0; i < 3; i++) {
        int first = (i == 0);
        int last  = (i == 2);
        const float* hin = hbuf[(i+1) & 1];
        float* hout      = hbuf[i & 1];
        fused_layer_mma<<<BT/64, 256, SMEM_FL>>>(
            hin, hout,
            pw_w + (size_t)i*C*C, pw_b + (size_t)i*C,
            ln2_g + (size_t)i*C, ln2_b + (size_t)i*C,
            sep_w + (size_t)i*C*3, sep_b + (size_t)i*C,
            ln1_g + (size_t)i*C, ln1_b + (size_t)i*C,
            mask, x, pre_w, pre_b,
            proj_w, proj_b, d, first, last);
        d *= 3;
    }

    spline_kernel<<<BT/256, 256>>>(x, mask, out);
    logdet_kernel<<<64, 256>>>(out + (size_t)BATCH*2*TLEN);
}